// round 1
// baseline (speedup 1.0000x reference)
#include <cuda_runtime.h>
#include <math.h>

#define HID 1024
#define NH 16
#define DH 64
#define TT 2048
#define TSEQ 2048
#define BB 4
#define MR (TT*BB)          // 8192 rows for projections
#define ROWSTR (BB*HID)     // 4096 floats per t-step

// ---------------- scratch (no cudaMalloc allowed) ----------------
__device__ float g_qh[(size_t)MR * HID];
__device__ float g_kh[(size_t)MR * HID];
__device__ float g_vh[(size_t)MR * HID];

// =================================================================
// Projection: Y = ReLU6(X @ W^T + bias)
// X: (MR, HID) row-major, W: (HID, HID) row-major (both K-contiguous)
// 128x128 tile, BK=16, 256 threads, 8x8 per thread (split 4+4)
// =================================================================
__global__ __launch_bounds__(256) void proj_kernel(
    const float* __restrict__ X, const float* __restrict__ W,
    const float* __restrict__ bias, float* __restrict__ Y)
{
    __shared__ float As[16][132];
    __shared__ float Bs[16][132];

    const int tx = threadIdx.x;          // 0..15
    const int ty = threadIdx.y;          // 0..15
    const int tid = ty * 16 + tx;
    const int m0 = blockIdx.y * 128;
    const int n0 = blockIdx.x * 128;

    float acc[8][8];
#pragma unroll
    for (int i = 0; i < 8; i++)
#pragma unroll
        for (int j = 0; j < 8; j++) acc[i][j] = 0.f;

    for (int k0 = 0; k0 < HID; k0 += 16) {
#pragma unroll
        for (int t = 0; t < 2; t++) {
            int f = tid + t * 256;          // 0..511
            int r = f >> 2;                 // 0..127
            int kc = (f & 3) * 4;           // 0,4,8,12
            float4 va = *reinterpret_cast<const float4*>(
                X + (size_t)(m0 + r) * HID + k0 + kc);
            As[kc + 0][r] = va.x; As[kc + 1][r] = va.y;
            As[kc + 2][r] = va.z; As[kc + 3][r] = va.w;
            float4 vb = *reinterpret_cast<const float4*>(
                W + (size_t)(n0 + r) * HID + k0 + kc);
            Bs[kc + 0][r] = vb.x; Bs[kc + 1][r] = vb.y;
            Bs[kc + 2][r] = vb.z; Bs[kc + 3][r] = vb.w;
        }
        __syncthreads();

#pragma unroll
        for (int kk = 0; kk < 16; kk++) {
            float a[8], b[8];
            float4 a0 = *reinterpret_cast<const float4*>(&As[kk][ty * 4]);
            float4 a1 = *reinterpret_cast<const float4*>(&As[kk][64 + ty * 4]);
            a[0]=a0.x; a[1]=a0.y; a[2]=a0.z; a[3]=a0.w;
            a[4]=a1.x; a[5]=a1.y; a[6]=a1.z; a[7]=a1.w;
            float4 b0 = *reinterpret_cast<const float4*>(&Bs[kk][tx * 4]);
            float4 b1 = *reinterpret_cast<const float4*>(&Bs[kk][64 + tx * 4]);
            b[0]=b0.x; b[1]=b0.y; b[2]=b0.z; b[3]=b0.w;
            b[4]=b1.x; b[5]=b1.y; b[6]=b1.z; b[7]=b1.w;
#pragma unroll
            for (int i = 0; i < 8; i++)
#pragma unroll
                for (int j = 0; j < 8; j++)
                    acc[i][j] += a[i] * b[j];
        }
        __syncthreads();
    }

    // epilogue: bias + relu6, vectorized stores
    float4 bia0 = *reinterpret_cast<const float4*>(bias + n0 + tx * 4);
    float4 bia1 = *reinterpret_cast<const float4*>(bias + n0 + 64 + tx * 4);
    float bj[8] = {bia0.x, bia0.y, bia0.z, bia0.w, bia1.x, bia1.y, bia1.z, bia1.w};
#pragma unroll
    for (int i = 0; i < 8; i++) {
        int r = m0 + ((i < 4) ? (ty * 4 + i) : (64 + ty * 4 + i - 4));
        float v[8];
#pragma unroll
        for (int j = 0; j < 8; j++)
            v[j] = fminf(fmaxf(acc[i][j] + bj[j], 0.f), 6.f);
        float4 o0 = {v[0], v[1], v[2], v[3]};
        float4 o1 = {v[4], v[5], v[6], v[7]};
        *reinterpret_cast<float4*>(Y + (size_t)r * HID + n0 + tx * 4) = o0;
        *reinterpret_cast<float4*>(Y + (size_t)r * HID + n0 + 64 + tx * 4) = o1;
    }
}

// =================================================================
// Flash attention, fp32, per (b,h): softmax(QK^T/8) V
// Block: 128 threads (8,16); Q tile = 64 rows; K tile = 64 cols.
// Register tile 4 rows x 8 cols per thread.
// =================================================================
#define QSTR 68
#define PSTR 68
#define SMF (64*QSTR*4 + 64*9 + 256)      // total floats
#define SMEM_BYTES (SMF * 4)

__global__ __launch_bounds__(128) void attn_kernel(
    const float* __restrict__ qh, const float* __restrict__ kh,
    const float* __restrict__ vh, float* __restrict__ out)
{
    extern __shared__ float sm[];
    float* Qs  = sm;                 // [64][QSTR]  (d, r) transposed
    float* Ks  = sm + 64 * QSTR;     // [64][QSTR]  (d, c) transposed
    float* Ps  = sm + 2 * 64 * QSTR; // [64][PSTR]  (r, kc) natural
    float* Vs  = sm + 3 * 64 * QSTR; // [64][PSTR]  (kc, d) natural
    float* red = sm + 4 * 64 * QSTR; // [64][9]
    float* mrun = red + 64 * 9;
    float* lrun = mrun + 64;
    float* mnew = mrun + 128;
    float* fsc  = mrun + 192;

    const int tx = threadIdx.x;          // 0..7
    const int ty = threadIdx.y;          // 0..15
    const int tid = ty * 8 + tx;
    const int b = blockIdx.z, h = blockIdx.y;
    const int q0 = blockIdx.x * 64;
    const size_t hoff = (size_t)b * HID + (size_t)h * DH;

    // load Q tile transposed: Qs[d][r]
#pragma unroll
    for (int t = 0; t < 8; t++) {
        int f = tid + t * 128;            // 0..1023
        int r = f >> 4;                   // 0..63
        int dc = (f & 15) * 4;            // 0..60
        float4 v = *reinterpret_cast<const float4*>(
            qh + (size_t)(q0 + r) * ROWSTR + hoff + dc);
        Qs[(dc + 0) * QSTR + r] = v.x; Qs[(dc + 1) * QSTR + r] = v.y;
        Qs[(dc + 2) * QSTR + r] = v.z; Qs[(dc + 3) * QSTR + r] = v.w;
    }
    if (tid < 64) { mrun[tid] = -1e30f; lrun[tid] = 0.f; }

    float O[4][8];
#pragma unroll
    for (int i = 0; i < 4; i++)
#pragma unroll
        for (int j = 0; j < 8; j++) O[i][j] = 0.f;
    __syncthreads();

    for (int s0 = 0; s0 < TSEQ; s0 += 64) {
        // load K tile transposed Ks[d][c]; V tile natural Vs[kc][d]
#pragma unroll
        for (int t = 0; t < 8; t++) {
            int f = tid + t * 128;
            int r = f >> 4;
            int dc = (f & 15) * 4;
            float4 vk = *reinterpret_cast<const float4*>(
                kh + (size_t)(s0 + r) * ROWSTR + hoff + dc);
            Ks[(dc + 0) * QSTR + r] = vk.x; Ks[(dc + 1) * QSTR + r] = vk.y;
            Ks[(dc + 2) * QSTR + r] = vk.z; Ks[(dc + 3) * QSTR + r] = vk.w;
            float4 vv = *reinterpret_cast<const float4*>(
                vh + (size_t)(s0 + r) * ROWSTR + hoff + dc);
            *reinterpret_cast<float4*>(&Vs[r * PSTR + dc]) = vv;
        }
        __syncthreads();

        // S = Q K^T
        float S[4][8];
#pragma unroll
        for (int i = 0; i < 4; i++)
#pragma unroll
            for (int j = 0; j < 8; j++) S[i][j] = 0.f;
#pragma unroll 8
        for (int d = 0; d < DH; d++) {
            float a[4], bv[8];
            float4 qa = *reinterpret_cast<const float4*>(&Qs[d * QSTR + ty * 4]);
            a[0]=qa.x; a[1]=qa.y; a[2]=qa.z; a[3]=qa.w;
            float4 k0 = *reinterpret_cast<const float4*>(&Ks[d * QSTR + tx * 4]);
            float4 k1 = *reinterpret_cast<const float4*>(&Ks[d * QSTR + 32 + tx * 4]);
            bv[0]=k0.x; bv[1]=k0.y; bv[2]=k0.z; bv[3]=k0.w;
            bv[4]=k1.x; bv[5]=k1.y; bv[6]=k1.z; bv[7]=k1.w;
#pragma unroll
            for (int i = 0; i < 4; i++)
#pragma unroll
                for (int j = 0; j < 8; j++)
                    S[i][j] += a[i] * bv[j];
        }

        // scale + per-thread row max
#pragma unroll
        for (int i = 0; i < 4; i++) {
            float mx = -1e30f;
#pragma unroll
            for (int j = 0; j < 8; j++) {
                S[i][j] *= 0.125f;
                mx = fmaxf(mx, S[i][j]);
            }
            red[(ty * 4 + i) * 9 + tx] = mx;
        }
        __syncthreads();

        if (tid < 64) {
            float mx = red[tid * 9 + 0];
#pragma unroll
            for (int t = 1; t < 8; t++) mx = fmaxf(mx, red[tid * 9 + t]);
            float mo = mrun[tid];
            float mn = fmaxf(mo, mx);
            mnew[tid] = mn;
            fsc[tid] = __expf(mo - mn);
            mrun[tid] = mn;
        }
        __syncthreads();

        // P = exp(S - m), write Ps, partial sums, rescale O
#pragma unroll
        for (int i = 0; i < 4; i++) {
            int r = ty * 4 + i;
            float mn = mnew[r];
            float4 p0, p1;
            p0.x = __expf(S[i][0] - mn); p0.y = __expf(S[i][1] - mn);
            p0.z = __expf(S[i][2] - mn); p0.w = __expf(S[i][3] - mn);
            p1.x = __expf(S[i][4] - mn); p1.y = __expf(S[i][5] - mn);
            p1.z = __expf(S[i][6] - mn); p1.w = __expf(S[i][7] - mn);
            *reinterpret_cast<float4*>(&Ps[r * PSTR + tx * 4]) = p0;
            *reinterpret_cast<float4*>(&Ps[r * PSTR + 32 + tx * 4]) = p1;
            red[r * 9 + tx] = p0.x + p0.y + p0.z + p0.w + p1.x + p1.y + p1.z + p1.w;
            float f = fsc[r];
#pragma unroll
            for (int j = 0; j < 8; j++) O[i][j] *= f;
        }
        __syncthreads();

        if (tid < 64) {
            float s = 0.f;
#pragma unroll
            for (int t = 0; t < 8; t++) s += red[tid * 9 + t];
            lrun[tid] = lrun[tid] * fsc[tid] + s;
        }

        // O += P @ V
#pragma unroll 8
        for (int kc = 0; kc < 64; kc++) {
            float a[4];
#pragma unroll
            for (int i = 0; i < 4; i++) a[i] = Ps[(ty * 4 + i) * PSTR + kc];
            float4 v0 = *reinterpret_cast<const float4*>(&Vs[kc * PSTR + tx * 4]);
            float4 v1 = *reinterpret_cast<const float4*>(&Vs[kc * PSTR + 32 + tx * 4]);
            float bv[8] = {v0.x, v0.y, v0.z, v0.w, v1.x, v1.y, v1.z, v1.w};
#pragma unroll
            for (int i = 0; i < 4; i++)
#pragma unroll
                for (int j = 0; j < 8; j++)
                    O[i][j] += a[i] * bv[j];
        }
        __syncthreads();
    }

    // epilogue: normalize and store
#pragma unroll
    for (int i = 0; i < 4; i++) {
        int r = ty * 4 + i;
        float il = 1.f / lrun[r];
        float4 o0 = {O[i][0] * il, O[i][1] * il, O[i][2] * il, O[i][3] * il};
        float4 o1 = {O[i][4] * il, O[i][5] * il, O[i][6] * il, O[i][7] * il};
        size_t base = (size_t)(q0 + r) * ROWSTR + hoff;
        *reinterpret_cast<float4*>(out + base + tx * 4) = o0;
        *reinterpret_cast<float4*>(out + base + 32 + tx * 4) = o1;
    }
}

// =================================================================
extern "C" void kernel_launch(void* const* d_in, const int* in_sizes, int n_in,
                              void* d_out, int out_size)
{
    const float* q  = (const float*)d_in[0];
    const float* k  = (const float*)d_in[1];
    const float* v  = (const float*)d_in[2];
    const float* Wq = (const float*)d_in[3];
    const float* bq = (const float*)d_in[4];
    const float* Wk = (const float*)d_in[5];
    const float* bk = (const float*)d_in[6];
    const float* Wv = (const float*)d_in[7];
    const float* bv = (const float*)d_in[8];
    float* out = (float*)d_out;

    float *qh, *kh, *vh;
    cudaGetSymbolAddress((void**)&qh, g_qh);
    cudaGetSymbolAddress((void**)&kh, g_kh);
    cudaGetSymbolAddress((void**)&vh, g_vh);

    dim3 pb(16, 16);
    dim3 pg(HID / 128, MR / 128);
    proj_kernel<<<pg, pb>>>(q, Wq, bq, qh);
    proj_kernel<<<pg, pb>>>(k, Wk, bk, kh);
    proj_kernel<<<pg, pb>>>(v, Wv, bv, vh);

    cudaFuncSetAttribute(attn_kernel,
                         cudaFuncAttributeMaxDynamicSharedMemorySize, SMEM_BYTES);
    dim3 ab(8, 16);
    dim3 ag(TT / 64, NH, BB);
    attn_kernel<<<ag, ab, SMEM_BYTES>>>(qh, kh, vh, out);
}

// round 2
// speedup vs baseline: 2.2898x; 2.2898x over previous
#include <cuda_runtime.h>
#include <cstdint>
#include <math.h>

#define HID 1024
#define NH 16
#define DH 64
#define TT 2048
#define TSEQ 2048
#define BB 4
#define MR (TT*BB)          // 8192 rows for projections
#define ROWSTR (BB*HID)     // 4096 floats per t-step

// ---------------- scratch (no cudaMalloc allowed) ----------------
__device__ float g_qh[(size_t)MR * HID];
__device__ float g_kh[(size_t)MR * HID];
__device__ float g_vh[(size_t)MR * HID];

// ---------------- tf32 helpers ----------------
__device__ __forceinline__ uint32_t f2tf(float x) {
    uint32_t r; asm("cvt.rna.tf32.f32 %0, %1;" : "=r"(r) : "f"(x)); return r;
}
__device__ __forceinline__ float f2tff(float x) { return __uint_as_float(f2tf(x)); }

// D = A(16x8) * B(8x8) + D, tf32 in, fp32 acc
__device__ __forceinline__ void mma_tf32(float* c, const uint32_t* a, const uint32_t* b) {
    asm volatile(
        "mma.sync.aligned.m16n8k8.row.col.f32.tf32.tf32.f32 "
        "{%0,%1,%2,%3}, {%4,%5,%6,%7}, {%8,%9}, {%0,%1,%2,%3};"
        : "+f"(c[0]), "+f"(c[1]), "+f"(c[2]), "+f"(c[3])
        : "r"(a[0]), "r"(a[1]), "r"(a[2]), "r"(a[3]), "r"(b[0]), "r"(b[1]));
}

// =================================================================
// Projection: Y = ReLU6(X @ W^T + bias), tf32 tensor-core GEMM
// 128x128 tile, K-tile 32, 256 threads (8 warps, 2x4 warp grid)
// smem layout [row][k] stride 36 -> bank(row*4+k) conflict-free frags
// =================================================================
#define PJS 36
__global__ __launch_bounds__(256) void proj_kernel(
    const float* __restrict__ X, const float* __restrict__ W,
    const float* __restrict__ bias, float* __restrict__ Y)
{
    __shared__ float As[128 * PJS];
    __shared__ float Bs[128 * PJS];

    const int tid = threadIdx.x;
    const int lane = tid & 31;
    const int wid = tid >> 5;
    const int g = lane >> 2;        // 0..7
    const int t = lane & 3;         // 0..3
    const int wm = (wid >> 2) * 64; // 0,64
    const int wn = (wid & 3) * 32;  // 0,32,64,96
    const int m0 = blockIdx.y * 128;
    const int n0 = blockIdx.x * 128;

    float acc[4][4][4];
#pragma unroll
    for (int mt = 0; mt < 4; mt++)
#pragma unroll
        for (int nt = 0; nt < 4; nt++)
#pragma unroll
            for (int j = 0; j < 4; j++) acc[mt][nt][j] = 0.f;

    const int lr = tid >> 3;          // 0..31
    const int lkc = (tid & 7) * 4;    // 0..28

    for (int k0 = 0; k0 < HID; k0 += 32) {
#pragma unroll
        for (int i = 0; i < 4; i++) {
            int row = lr + i * 32;
            float4 va = *reinterpret_cast<const float4*>(X + (size_t)(m0 + row) * HID + k0 + lkc);
            float* a = &As[row * PJS + lkc];
            a[0] = f2tff(va.x); a[1] = f2tff(va.y); a[2] = f2tff(va.z); a[3] = f2tff(va.w);
            float4 vb = *reinterpret_cast<const float4*>(W + (size_t)(n0 + row) * HID + k0 + lkc);
            float* bq = &Bs[row * PJS + lkc];
            bq[0] = f2tff(vb.x); bq[1] = f2tff(vb.y); bq[2] = f2tff(vb.z); bq[3] = f2tff(vb.w);
        }
        __syncthreads();

#pragma unroll
        for (int kk = 0; kk < 32; kk += 8) {
            uint32_t af[4][4], bf[4][2];
#pragma unroll
            for (int mt = 0; mt < 4; mt++) {
                int rb = wm + mt * 16;
                af[mt][0] = __float_as_uint(As[(rb + g)     * PJS + kk + t]);
                af[mt][1] = __float_as_uint(As[(rb + g + 8) * PJS + kk + t]);
                af[mt][2] = __float_as_uint(As[(rb + g)     * PJS + kk + t + 4]);
                af[mt][3] = __float_as_uint(As[(rb + g + 8) * PJS + kk + t + 4]);
            }
#pragma unroll
            for (int nt = 0; nt < 4; nt++) {
                int rb = wn + nt * 8 + g;
                bf[nt][0] = __float_as_uint(Bs[rb * PJS + kk + t]);
                bf[nt][1] = __float_as_uint(Bs[rb * PJS + kk + t + 4]);
            }
#pragma unroll
            for (int mt = 0; mt < 4; mt++)
#pragma unroll
                for (int nt = 0; nt < 4; nt++)
                    mma_tf32(acc[mt][nt], af[mt], bf[nt]);
        }
        __syncthreads();
    }

    // epilogue: bias + relu6
#pragma unroll
    for (int nt = 0; nt < 4; nt++) {
        int col = n0 + wn + nt * 8 + 2 * t;
        float b0 = bias[col], b1 = bias[col + 1];
#pragma unroll
        for (int mt = 0; mt < 4; mt++) {
            int r0 = m0 + wm + mt * 16 + g;
            float2 o0, o1;
            o0.x = fminf(fmaxf(acc[mt][nt][0] + b0, 0.f), 6.f);
            o0.y = fminf(fmaxf(acc[mt][nt][1] + b1, 0.f), 6.f);
            o1.x = fminf(fmaxf(acc[mt][nt][2] + b0, 0.f), 6.f);
            o1.y = fminf(fmaxf(acc[mt][nt][3] + b1, 0.f), 6.f);
            *reinterpret_cast<float2*>(Y + (size_t)r0 * HID + col) = o0;
            *reinterpret_cast<float2*>(Y + (size_t)(r0 + 8) * HID + col) = o1;
        }
    }
}

// =================================================================
// Flash attention, tf32 tensor cores.
// Block: 256 threads (8 warps). Q tile = 128 rows (16 per warp),
// K tile = 64. Q fragments persistent in registers. Softmax fully
// in registers via quad shuffles. P staged in warp-private smem rows.
// =================================================================
#define AST 68
#define ATT_SMEM ((128*AST + 64*AST + 64*AST) * 4)   // 69632 B

__global__ __launch_bounds__(256) void attn_kernel(
    const float* __restrict__ qh, const float* __restrict__ kh,
    const float* __restrict__ vh, float* __restrict__ out)
{
    extern __shared__ float sm[];
    float* Ps = sm;                  // [128][AST]  (Q staging, then P)
    float* Kn = sm + 128 * AST;      // [64][AST]   K natural [s][d]
    float* Vs = Kn + 64 * AST;       // [64][AST]   V natural [s][d]

    const int tid = threadIdx.x;
    const int lane = tid & 31;
    const int wid = tid >> 5;        // 0..7
    const int g = lane >> 2;
    const int t = lane & 3;
    const int b = blockIdx.z, h = blockIdx.y;
    const int q0 = blockIdx.x * 128;
    const size_t hoff = (size_t)b * HID + (size_t)h * DH;
    const int wrow = wid * 16;       // warp's base row in tile

    // ---- stage Q (tf32) into Ps region ----
#pragma unroll
    for (int i = 0; i < 8; i++) {
        int f = tid + i * 256;            // 0..2047
        int row = f >> 4;                 // 0..127
        int dc = (f & 15) * 4;
        float4 v = *reinterpret_cast<const float4*>(
            qh + (size_t)(q0 + row) * ROWSTR + hoff + dc);
        float4 c = {f2tff(v.x), f2tff(v.y), f2tff(v.z), f2tff(v.w)};
        *reinterpret_cast<float4*>(&Ps[row * AST + dc]) = c;
    }
    __syncthreads();

    // ---- persistent Q fragments: 8 k-steps x 4 regs ----
    uint32_t qa[8][4];
#pragma unroll
    for (int ks = 0; ks < 8; ks++) {
        qa[ks][0] = __float_as_uint(Ps[(wrow + g)     * AST + ks * 8 + t]);
        qa[ks][1] = __float_as_uint(Ps[(wrow + g + 8) * AST + ks * 8 + t]);
        qa[ks][2] = __float_as_uint(Ps[(wrow + g)     * AST + ks * 8 + t + 4]);
        qa[ks][3] = __float_as_uint(Ps[(wrow + g + 8) * AST + ks * 8 + t + 4]);
    }
    // (warp-private rows: this warp only ever re-writes its own rows as P)

    float O[8][4];
#pragma unroll
    for (int nt = 0; nt < 8; nt++)
#pragma unroll
        for (int j = 0; j < 4; j++) O[nt][j] = 0.f;
    float m0r = -1e30f, m1r = -1e30f, l0 = 0.f, l1 = 0.f;

    for (int s0 = 0; s0 < TSEQ; s0 += 64) {
        // ---- load K, V tiles (tf32) ----
#pragma unroll
        for (int i = 0; i < 4; i++) {
            int f = tid + i * 256;          // 0..1023
            int row = f >> 4;               // 0..63
            int dc = (f & 15) * 4;
            float4 vk = *reinterpret_cast<const float4*>(
                kh + (size_t)(s0 + row) * ROWSTR + hoff + dc);
            float4 ck = {f2tff(vk.x), f2tff(vk.y), f2tff(vk.z), f2tff(vk.w)};
            *reinterpret_cast<float4*>(&Kn[row * AST + dc]) = ck;
            float4 vv = *reinterpret_cast<const float4*>(
                vh + (size_t)(s0 + row) * ROWSTR + hoff + dc);
            float4 cv = {f2tff(vv.x), f2tff(vv.y), f2tff(vv.z), f2tff(vv.w)};
            *reinterpret_cast<float4*>(&Vs[row * AST + dc]) = cv;
        }
        __syncthreads();

        // ---- S = Q K^T  (per-warp 16x64) ----
        float sacc[8][4];
#pragma unroll
        for (int nt = 0; nt < 8; nt++) {
#pragma unroll
            for (int j = 0; j < 4; j++) sacc[nt][j] = 0.f;
            int srow = nt * 8 + g;
#pragma unroll
            for (int ks = 0; ks < 8; ks++) {
                uint32_t bf[2];
                bf[0] = __float_as_uint(Kn[srow * AST + ks * 8 + t]);
                bf[1] = __float_as_uint(Kn[srow * AST + ks * 8 + t + 4]);
                mma_tf32(sacc[nt], qa[ks], bf);
            }
        }

        // ---- online softmax (registers + quad shuffles) ----
        float mx0 = -1e30f, mx1 = -1e30f;
#pragma unroll
        for (int nt = 0; nt < 8; nt++) {
#pragma unroll
            for (int j = 0; j < 4; j++) sacc[nt][j] *= 0.125f;
            mx0 = fmaxf(mx0, fmaxf(sacc[nt][0], sacc[nt][1]));
            mx1 = fmaxf(mx1, fmaxf(sacc[nt][2], sacc[nt][3]));
        }
        mx0 = fmaxf(mx0, __shfl_xor_sync(0xffffffff, mx0, 1));
        mx0 = fmaxf(mx0, __shfl_xor_sync(0xffffffff, mx0, 2));
        mx1 = fmaxf(mx1, __shfl_xor_sync(0xffffffff, mx1, 1));
        mx1 = fmaxf(mx1, __shfl_xor_sync(0xffffffff, mx1, 2));

        float mn0 = fmaxf(m0r, mx0), mn1 = fmaxf(m1r, mx1);
        float f0 = __expf(m0r - mn0), f1 = __expf(m1r - mn1);
        m0r = mn0; m1r = mn1;

        float s0s = 0.f, s1s = 0.f;
        const int r0 = wrow + g, r1 = wrow + g + 8;
#pragma unroll
        for (int nt = 0; nt < 8; nt++) {
            float p0 = __expf(sacc[nt][0] - mn0);
            float p1 = __expf(sacc[nt][1] - mn0);
            float p2 = __expf(sacc[nt][2] - mn1);
            float p3 = __expf(sacc[nt][3] - mn1);
            s0s += p0 + p1; s1s += p2 + p3;
            float2 w0 = {f2tff(p0), f2tff(p1)};
            float2 w1 = {f2tff(p2), f2tff(p3)};
            *reinterpret_cast<float2*>(&Ps[r0 * AST + nt * 8 + 2 * t]) = w0;
            *reinterpret_cast<float2*>(&Ps[r1 * AST + nt * 8 + 2 * t]) = w1;
        }
        s0s += __shfl_xor_sync(0xffffffff, s0s, 1);
        s0s += __shfl_xor_sync(0xffffffff, s0s, 2);
        s1s += __shfl_xor_sync(0xffffffff, s1s, 1);
        s1s += __shfl_xor_sync(0xffffffff, s1s, 2);
        l0 = l0 * f0 + s0s;
        l1 = l1 * f1 + s1s;
#pragma unroll
        for (int nt = 0; nt < 8; nt++) {
            O[nt][0] *= f0; O[nt][1] *= f0;
            O[nt][2] *= f1; O[nt][3] *= f1;
        }

        // ---- O += P V  (per-warp 16x64) ----
#pragma unroll
        for (int ks = 0; ks < 8; ks++) {
            uint32_t pa[4];
            pa[0] = __float_as_uint(Ps[r0 * AST + ks * 8 + t]);
            pa[1] = __float_as_uint(Ps[r1 * AST + ks * 8 + t]);
            pa[2] = __float_as_uint(Ps[r0 * AST + ks * 8 + t + 4]);
            pa[3] = __float_as_uint(Ps[r1 * AST + ks * 8 + t + 4]);
#pragma unroll
            for (int nt = 0; nt < 8; nt++) {
                uint32_t bf[2];
                bf[0] = __float_as_uint(Vs[(ks * 8 + t)     * AST + nt * 8 + g]);
                bf[1] = __float_as_uint(Vs[(ks * 8 + t + 4) * AST + nt * 8 + g]);
                mma_tf32(O[nt], pa, bf);
            }
        }
        __syncthreads();
    }

    // ---- epilogue: normalize + store ----
    float il0 = 1.f / l0, il1 = 1.f / l1;
    const int gr0 = q0 + wrow + g, gr1 = gr0 + 8;
#pragma unroll
    for (int nt = 0; nt < 8; nt++) {
        int col = nt * 8 + 2 * t;
        float2 o0 = {O[nt][0] * il0, O[nt][1] * il0};
        float2 o1 = {O[nt][2] * il1, O[nt][3] * il1};
        *reinterpret_cast<float2*>(out + (size_t)gr0 * ROWSTR + hoff + col) = o0;
        *reinterpret_cast<float2*>(out + (size_t)gr1 * ROWSTR + hoff + col) = o1;
    }
}

// =================================================================
extern "C" void kernel_launch(void* const* d_in, const int* in_sizes, int n_in,
                              void* d_out, int out_size)
{
    const float* q  = (const float*)d_in[0];
    const float* k  = (const float*)d_in[1];
    const float* v  = (const float*)d_in[2];
    const float* Wq = (const float*)d_in[3];
    const float* bq = (const float*)d_in[4];
    const float* Wk = (const float*)d_in[5];
    const float* bk = (const float*)d_in[6];
    const float* Wv = (const float*)d_in[7];
    const float* bv = (const float*)d_in[8];
    float* out = (float*)d_out;

    float *qh, *kh, *vh;
    cudaGetSymbolAddress((void**)&qh, g_qh);
    cudaGetSymbolAddress((void**)&kh, g_kh);
    cudaGetSymbolAddress((void**)&vh, g_vh);

    dim3 pg(HID / 128, MR / 128);
    proj_kernel<<<pg, 256>>>(q, Wq, bq, qh);
    proj_kernel<<<pg, 256>>>(k, Wk, bk, kh);
    proj_kernel<<<pg, 256>>>(v, Wv, bv, vh);

    cudaFuncSetAttribute(attn_kernel,
                         cudaFuncAttributeMaxDynamicSharedMemorySize, ATT_SMEM);
    dim3 ag(TT / 128, NH, BB);
    attn_kernel<<<ag, 256, ATT_SMEM>>>(qh, kh, vh, out);
}

// round 3
// speedup vs baseline: 5.2415x; 2.2891x over previous
#include <cuda_runtime.h>
#include <cuda_bf16.h>
#include <cstdint>

#define HID 1024
#define NH 16
#define DH 64
#define TT 2048
#define TSEQ 2048
#define BB 4
#define MR (TT*BB)          // 8192 rows for projections
#define ROWSTR (BB*HID)     // 4096 elements per t-step

// ---------------- scratch (bf16 now) ----------------
__device__ __nv_bfloat16 g_qh[(size_t)MR * HID];
__device__ __nv_bfloat16 g_kh[(size_t)MR * HID];
__device__ __nv_bfloat16 g_vh[(size_t)MR * HID];

// ---------------- helpers ----------------
__device__ __forceinline__ uint32_t pack_bf16(float lo, float hi) {
    uint32_t d;
    asm("cvt.rn.bf16x2.f32 %0, %1, %2;" : "=r"(d) : "f"(hi), "f"(lo));
    return d;
}
__device__ __forceinline__ uint32_t smem_u32(const void* p) {
    return (uint32_t)__cvta_generic_to_shared(p);
}
__device__ __forceinline__ void ldsm_x4(uint32_t& r0, uint32_t& r1,
                                        uint32_t& r2, uint32_t& r3, uint32_t a) {
    asm volatile("ldmatrix.sync.aligned.m8n8.x4.shared.b16 {%0,%1,%2,%3}, [%4];"
                 : "=r"(r0), "=r"(r1), "=r"(r2), "=r"(r3) : "r"(a));
}
__device__ __forceinline__ void ldsm_x4t(uint32_t& r0, uint32_t& r1,
                                         uint32_t& r2, uint32_t& r3, uint32_t a) {
    asm volatile("ldmatrix.sync.aligned.m8n8.x4.trans.shared.b16 {%0,%1,%2,%3}, [%4];"
                 : "=r"(r0), "=r"(r1), "=r"(r2), "=r"(r3) : "r"(a));
}
__device__ __forceinline__ void mma_bf16(float* c, const uint32_t* a, const uint32_t* b) {
    asm volatile(
        "mma.sync.aligned.m16n8k16.row.col.f32.bf16.bf16.f32 "
        "{%0,%1,%2,%3}, {%4,%5,%6,%7}, {%8,%9}, {%0,%1,%2,%3};"
        : "+f"(c[0]), "+f"(c[1]), "+f"(c[2]), "+f"(c[3])
        : "r"(a[0]), "r"(a[1]), "r"(a[2]), "r"(a[3]), "r"(b[0]), "r"(b[1]));
}
__device__ __forceinline__ void cp16(uint32_t dst, const void* src) {
    asm volatile("cp.async.cg.shared.global [%0], [%1], 16;" :: "r"(dst), "l"(src) : "memory");
}
__device__ __forceinline__ void cp_commit() {
    asm volatile("cp.async.commit_group;" ::: "memory");
}
template <int N> __device__ __forceinline__ void cp_wait() {
    asm volatile("cp.async.wait_group %0;" :: "n"(N) : "memory");
}

// =================================================================
// Projection: Y = ReLU6(X @ W^T + bias) * scale  ->  bf16
// 128x128 tile, BK=32, 256 threads (8 warps, 2x4), bf16 m16n8k16
// smem [row][k] stride 40 b16 (80B) -> conflict-free ldmatrix
// =================================================================
#define PJS 40
__global__ __launch_bounds__(256, 2) void proj_kernel(
    const float* __restrict__ X, const float* __restrict__ W,
    const float* __restrict__ bias, __nv_bfloat16* __restrict__ Y, float scale)
{
    __shared__ __align__(16) uint16_t As[128 * PJS];
    __shared__ __align__(16) uint16_t Bs[128 * PJS];

    const int tid = threadIdx.x;
    const int lane = tid & 31;
    const int wid = tid >> 5;
    const int g = lane >> 2;
    const int t = lane & 3;
    const int wm = (wid >> 2) * 64;
    const int wn = (wid & 3) * 32;
    const int m0 = blockIdx.y * 128;
    const int n0 = blockIdx.x * 128;

    float acc[4][4][4];
#pragma unroll
    for (int mt = 0; mt < 4; mt++)
#pragma unroll
        for (int nt = 0; nt < 4; nt++)
#pragma unroll
            for (int j = 0; j < 4; j++) acc[mt][nt][j] = 0.f;

    for (int k0 = 0; k0 < HID; k0 += 32) {
#pragma unroll
        for (int i = 0; i < 4; i++) {
            int f = tid + i * 256;          // 0..1023
            int row = f >> 3;               // 0..127
            int kc = (f & 7) * 4;           // 0..28
            float4 va = *reinterpret_cast<const float4*>(
                X + (size_t)(m0 + row) * HID + k0 + kc);
            *reinterpret_cast<uint2*>(&As[row * PJS + kc]) =
                make_uint2(pack_bf16(va.x, va.y), pack_bf16(va.z, va.w));
            float4 vb = *reinterpret_cast<const float4*>(
                W + (size_t)(n0 + row) * HID + k0 + kc);
            *reinterpret_cast<uint2*>(&Bs[row * PJS + kc]) =
                make_uint2(pack_bf16(vb.x, vb.y), pack_bf16(vb.z, vb.w));
        }
        __syncthreads();

#pragma unroll
        for (int kt = 0; kt < 2; kt++) {
            uint32_t af[4][4], bf[4][2];
#pragma unroll
            for (int mt = 0; mt < 4; mt++)
                ldsm_x4(af[mt][0], af[mt][1], af[mt][2], af[mt][3],
                        smem_u32(&As[(wm + mt * 16 + (lane & 15)) * PJS +
                                     kt * 16 + (lane >> 4) * 8]));
#pragma unroll
            for (int ntp = 0; ntp < 2; ntp++) {
                uint32_t r0, r1, r2, r3;
                ldsm_x4(r0, r1, r2, r3,
                        smem_u32(&Bs[(wn + ntp * 16 + (lane & 7) + (lane >> 4) * 8) * PJS +
                                     kt * 16 + ((lane >> 3) & 1) * 8]));
                bf[2 * ntp][0] = r0; bf[2 * ntp][1] = r1;
                bf[2 * ntp + 1][0] = r2; bf[2 * ntp + 1][1] = r3;
            }
#pragma unroll
            for (int mt = 0; mt < 4; mt++)
#pragma unroll
                for (int nt = 0; nt < 4; nt++)
                    mma_bf16(acc[mt][nt], af[mt], bf[nt]);
        }
        __syncthreads();
    }

    // epilogue: bias + relu6 + scale -> bf16
#pragma unroll
    for (int nt = 0; nt < 4; nt++) {
        int col = n0 + wn + nt * 8 + 2 * t;
        float b0 = bias[col], b1 = bias[col + 1];
#pragma unroll
        for (int mt = 0; mt < 4; mt++) {
            int r0 = m0 + wm + mt * 16 + g;
            float o0 = fminf(fmaxf(acc[mt][nt][0] + b0, 0.f), 6.f) * scale;
            float o1 = fminf(fmaxf(acc[mt][nt][1] + b1, 0.f), 6.f) * scale;
            float o2 = fminf(fmaxf(acc[mt][nt][2] + b0, 0.f), 6.f) * scale;
            float o3 = fminf(fmaxf(acc[mt][nt][3] + b1, 0.f), 6.f) * scale;
            *reinterpret_cast<uint32_t*>(Y + (size_t)r0 * HID + col) = pack_bf16(o0, o1);
            *reinterpret_cast<uint32_t*>(Y + (size_t)(r0 + 8) * HID + col) = pack_bf16(o2, o3);
        }
    }
}

// =================================================================
// Flash attention, bf16 tensor cores + ldmatrix + cp.async ping-pong.
// 256 threads (8 warps), Q tile = 128 (16 rows/warp), K tile = 64.
// Q frags persistent; P stays in registers (frag-layout identity).
// =================================================================
#define AKS 72
#define QS_OFF 0
#define KB_OFF (128 * AKS * 2)                 // 18432
#define VB_OFF (KB_OFF + 2 * 64 * AKS * 2)     // 36864
#define ATT_SMEM (VB_OFF + 2 * 64 * AKS * 2)   // 55296

__global__ __launch_bounds__(256, 2) void attn_kernel(
    const __nv_bfloat16* __restrict__ qh, const __nv_bfloat16* __restrict__ kh,
    const __nv_bfloat16* __restrict__ vh, float* __restrict__ out)
{
    extern __shared__ __align__(16) char sm[];
    uint16_t* QS = reinterpret_cast<uint16_t*>(sm + QS_OFF);   // [128][AKS]
    uint16_t* KB = reinterpret_cast<uint16_t*>(sm + KB_OFF);   // [2][64][AKS]
    uint16_t* VB = reinterpret_cast<uint16_t*>(sm + VB_OFF);   // [2][64][AKS]

    const int tid = threadIdx.x;
    const int lane = tid & 31;
    const int wid = tid >> 5;
    const int g = lane >> 2;
    const int t = lane & 3;
    const int b = blockIdx.z, h = blockIdx.y;
    const int q0 = blockIdx.x * 128;
    const size_t hoff = (size_t)b * HID + (size_t)h * DH;
    const int wrow = wid * 16;

    // ---- group 0: stage Q + K/V tile 0 ----
#pragma unroll
    for (int i = 0; i < 4; i++) {
        int f = tid + i * 256;            // 0..1023
        int row = f >> 3;                 // 0..127
        int dc = (f & 7) * 8;             // 0..56
        cp16(smem_u32(&QS[row * AKS + dc]),
             qh + (size_t)(q0 + row) * ROWSTR + hoff + dc);
    }
#pragma unroll
    for (int i = 0; i < 2; i++) {
        int f = tid + i * 256;            // 0..511
        int row = f >> 3;                 // 0..63
        int dc = (f & 7) * 8;
        cp16(smem_u32(&KB[row * AKS + dc]), kh + (size_t)row * ROWSTR + hoff + dc);
        cp16(smem_u32(&VB[row * AKS + dc]), vh + (size_t)row * ROWSTR + hoff + dc);
    }
    cp_commit();
    cp_wait<0>();
    __syncthreads();

    // ---- persistent Q fragments ----
    uint32_t qa[4][4];
#pragma unroll
    for (int kt = 0; kt < 4; kt++)
        ldsm_x4(qa[kt][0], qa[kt][1], qa[kt][2], qa[kt][3],
                smem_u32(&QS[(wrow + (lane & 15)) * AKS + kt * 16 + (lane >> 4) * 8]));

    float O[8][4];
#pragma unroll
    for (int nt = 0; nt < 8; nt++)
#pragma unroll
        for (int j = 0; j < 4; j++) O[nt][j] = 0.f;
    float m0r = -1e30f, m1r = -1e30f, l0 = 0.f, l1 = 0.f;

    for (int it = 0; it < TSEQ / 64; it++) {
        const int cur = it & 1;
        uint16_t* Kc = KB + cur * 64 * AKS;
        uint16_t* Vc = VB + cur * 64 * AKS;

        if (it < TSEQ / 64 - 1) {
            int s0n = (it + 1) * 64;
            uint16_t* Kn = KB + (cur ^ 1) * 64 * AKS;
            uint16_t* Vn = VB + (cur ^ 1) * 64 * AKS;
#pragma unroll
            for (int i = 0; i < 2; i++) {
                int f = tid + i * 256;
                int row = f >> 3;
                int dc = (f & 7) * 8;
                cp16(smem_u32(&Kn[row * AKS + dc]),
                     kh + (size_t)(s0n + row) * ROWSTR + hoff + dc);
                cp16(smem_u32(&Vn[row * AKS + dc]),
                     vh + (size_t)(s0n + row) * ROWSTR + hoff + dc);
            }
            cp_commit();
            cp_wait<1>();
        } else {
            cp_wait<0>();
        }
        __syncthreads();

        // ---- S = Q K^T (pre-scaled Q) ----
        float sacc[8][4];
#pragma unroll
        for (int nt = 0; nt < 8; nt++)
#pragma unroll
            for (int j = 0; j < 4; j++) sacc[nt][j] = 0.f;
#pragma unroll
        for (int ntp = 0; ntp < 4; ntp++) {
#pragma unroll
            for (int kt = 0; kt < 4; kt++) {
                uint32_t r0, r1, r2, r3;
                ldsm_x4(r0, r1, r2, r3,
                        smem_u32(&Kc[((lane & 7) + (lane >> 4) * 8 + ntp * 16) * AKS +
                                     kt * 16 + ((lane >> 3) & 1) * 8]));
                uint32_t blo[2] = {r0, r1}, bhi[2] = {r2, r3};
                mma_bf16(sacc[2 * ntp], qa[kt], blo);
                mma_bf16(sacc[2 * ntp + 1], qa[kt], bhi);
            }
        }

        // ---- online softmax in registers ----
        float mx0 = -1e30f, mx1 = -1e30f;
#pragma unroll
        for (int nt = 0; nt < 8; nt++) {
            mx0 = fmaxf(mx0, fmaxf(sacc[nt][0], sacc[nt][1]));
            mx1 = fmaxf(mx1, fmaxf(sacc[nt][2], sacc[nt][3]));
        }
        mx0 = fmaxf(mx0, __shfl_xor_sync(0xffffffff, mx0, 1));
        mx0 = fmaxf(mx0, __shfl_xor_sync(0xffffffff, mx0, 2));
        mx1 = fmaxf(mx1, __shfl_xor_sync(0xffffffff, mx1, 1));
        mx1 = fmaxf(mx1, __shfl_xor_sync(0xffffffff, mx1, 2));

        float mn0 = fmaxf(m0r, mx0), mn1 = fmaxf(m1r, mx1);
        float f0 = __expf(m0r - mn0), f1 = __expf(m1r - mn1);
        m0r = mn0; m1r = mn1;

        uint32_t pa[4][4];
        float s0s = 0.f, s1s = 0.f;
#pragma unroll
        for (int nt = 0; nt < 8; nt++) {
            float p0 = __expf(sacc[nt][0] - mn0);
            float p1 = __expf(sacc[nt][1] - mn0);
            float p2 = __expf(sacc[nt][2] - mn1);
            float p3 = __expf(sacc[nt][3] - mn1);
            s0s += p0 + p1; s1s += p2 + p3;
            int kt = nt >> 1;
            if ((nt & 1) == 0) {
                pa[kt][0] = pack_bf16(p0, p1);   // rows g,   k=16kt+2t..
                pa[kt][1] = pack_bf16(p2, p3);   // rows g+8
            } else {
                pa[kt][2] = pack_bf16(p0, p1);   // rows g,   k=16kt+8+2t
                pa[kt][3] = pack_bf16(p2, p3);   // rows g+8
            }
        }
        s0s += __shfl_xor_sync(0xffffffff, s0s, 1);
        s0s += __shfl_xor_sync(0xffffffff, s0s, 2);
        s1s += __shfl_xor_sync(0xffffffff, s1s, 1);
        s1s += __shfl_xor_sync(0xffffffff, s1s, 2);
        l0 = l0 * f0 + s0s;
        l1 = l1 * f1 + s1s;
#pragma unroll
        for (int nt = 0; nt < 8; nt++) {
            O[nt][0] *= f0; O[nt][1] *= f0;
            O[nt][2] *= f1; O[nt][3] *= f1;
        }

        // ---- O += P V ----
#pragma unroll
        for (int ntp = 0; ntp < 4; ntp++) {
#pragma unroll
            for (int kt = 0; kt < 4; kt++) {
                uint32_t r0, r1, r2, r3;
                ldsm_x4t(r0, r1, r2, r3,
                         smem_u32(&Vc[((lane & 7) + ((lane >> 3) & 1) * 8 + kt * 16) * AKS +
                                      ntp * 16 + (lane >> 4) * 8]));
                uint32_t blo[2] = {r0, r1}, bhi[2] = {r2, r3};
                mma_bf16(O[2 * ntp], pa[kt], blo);
                mma_bf16(O[2 * ntp + 1], pa[kt], bhi);
            }
        }
        __syncthreads();
    }

    // ---- epilogue: normalize + store fp32 ----
    float il0 = 1.f / l0, il1 = 1.f / l1;
    const int gr0 = q0 + wrow + g, gr1 = gr0 + 8;
#pragma unroll
    for (int nt = 0; nt < 8; nt++) {
        int col = nt * 8 + 2 * t;
        float2 o0 = {O[nt][0] * il0, O[nt][1] * il0};
        float2 o1 = {O[nt][2] * il1, O[nt][3] * il1};
        *reinterpret_cast<float2*>(out + (size_t)gr0 * ROWSTR + hoff + col) = o0;
        *reinterpret_cast<float2*>(out + (size_t)gr1 * ROWSTR + hoff + col) = o1;
    }
}

// =================================================================
extern "C" void kernel_launch(void* const* d_in, const int* in_sizes, int n_in,
                              void* d_out, int out_size)
{
    const float* q  = (const float*)d_in[0];
    const float* k  = (const float*)d_in[1];
    const float* v  = (const float*)d_in[2];
    const float* Wq = (const float*)d_in[3];
    const float* bq = (const float*)d_in[4];
    const float* Wk = (const float*)d_in[5];
    const float* bk = (const float*)d_in[6];
    const float* Wv = (const float*)d_in[7];
    const float* bv = (const float*)d_in[8];
    float* out = (float*)d_out;

    __nv_bfloat16 *qh, *kh, *vh;
    cudaGetSymbolAddress((void**)&qh, g_qh);
    cudaGetSymbolAddress((void**)&kh, g_kh);
    cudaGetSymbolAddress((void**)&vh, g_vh);

    dim3 pg(HID / 128, MR / 128);
    proj_kernel<<<pg, 256>>>(q, Wq, bq, qh, 0.125f);   // fold 1/sqrt(d) into Q
    proj_kernel<<<pg, 256>>>(k, Wk, bk, kh, 1.0f);
    proj_kernel<<<pg, 256>>>(v, Wv, bv, vh, 1.0f);

    cudaFuncSetAttribute(attn_kernel,
                         cudaFuncAttributeMaxDynamicSharedMemorySize, ATT_SMEM);
    dim3 ag(TT / 128, NH, BB);
    attn_kernel<<<ag, 256, ATT_SMEM>>>(qh, kh, vh, out);
}

// round 4
// speedup vs baseline: 6.5115x; 1.2423x over previous
#include <cuda_runtime.h>
#include <cuda_bf16.h>
#include <cstdint>

#define HID 1024
#define NH 16
#define DH 64
#define TT 2048
#define TSEQ 2048
#define BB 4
#define MR (TT*BB)          // 8192 rows for projections
#define ROWSTR (BB*HID)     // 4096 elements per t-step
#define LOG2E 1.4426950408889634f

// ---------------- scratch ----------------
__device__ __nv_bfloat16 g_qh[(size_t)MR * HID];
__device__ __nv_bfloat16 g_kh[(size_t)MR * HID];
__device__ __nv_bfloat16 g_vh[(size_t)MR * HID];
__device__ __nv_bfloat16 g_xq[(size_t)MR * HID];
__device__ __nv_bfloat16 g_xk[(size_t)MR * HID];
__device__ __nv_bfloat16 g_xv[(size_t)MR * HID];
__device__ __nv_bfloat16 g_wq[(size_t)HID * HID];
__device__ __nv_bfloat16 g_wk[(size_t)HID * HID];
__device__ __nv_bfloat16 g_wv[(size_t)HID * HID];

// ---------------- helpers ----------------
__device__ __forceinline__ uint32_t pack_bf16(float lo, float hi) {
    uint32_t d;
    asm("cvt.rn.bf16x2.f32 %0, %1, %2;" : "=r"(d) : "f"(hi), "f"(lo));
    return d;
}
__device__ __forceinline__ float ex2(float x) {
    float r; asm("ex2.approx.f32 %0, %1;" : "=f"(r) : "f"(x)); return r;
}
__device__ __forceinline__ uint32_t smem_u32(const void* p) {
    return (uint32_t)__cvta_generic_to_shared(p);
}
__device__ __forceinline__ void ldsm_x4(uint32_t& r0, uint32_t& r1,
                                        uint32_t& r2, uint32_t& r3, uint32_t a) {
    asm volatile("ldmatrix.sync.aligned.m8n8.x4.shared.b16 {%0,%1,%2,%3}, [%4];"
                 : "=r"(r0), "=r"(r1), "=r"(r2), "=r"(r3) : "r"(a));
}
__device__ __forceinline__ void ldsm_x4t(uint32_t& r0, uint32_t& r1,
                                         uint32_t& r2, uint32_t& r3, uint32_t a) {
    asm volatile("ldmatrix.sync.aligned.m8n8.x4.trans.shared.b16 {%0,%1,%2,%3}, [%4];"
                 : "=r"(r0), "=r"(r1), "=r"(r2), "=r"(r3) : "r"(a));
}
__device__ __forceinline__ void ldsm_x2t(uint32_t& r0, uint32_t& r1, uint32_t a) {
    asm volatile("ldmatrix.sync.aligned.m8n8.x2.trans.shared.b16 {%0,%1}, [%2];"
                 : "=r"(r0), "=r"(r1) : "r"(a));
}
__device__ __forceinline__ void mma_bf16(float* c, const uint32_t* a, const uint32_t* b) {
    asm volatile(
        "mma.sync.aligned.m16n8k16.row.col.f32.bf16.bf16.f32 "
        "{%0,%1,%2,%3}, {%4,%5,%6,%7}, {%8,%9}, {%0,%1,%2,%3};"
        : "+f"(c[0]), "+f"(c[1]), "+f"(c[2]), "+f"(c[3])
        : "r"(a[0]), "r"(a[1]), "r"(a[2]), "r"(a[3]), "r"(b[0]), "r"(b[1]));
}
__device__ __forceinline__ void cp16(uint32_t dst, const void* src) {
    asm volatile("cp.async.cg.shared.global [%0], [%1], 16;" :: "r"(dst), "l"(src) : "memory");
}
__device__ __forceinline__ void cp_commit() {
    asm volatile("cp.async.commit_group;" ::: "memory");
}
template <int N> __device__ __forceinline__ void cp_wait() {
    asm volatile("cp.async.wait_group %0;" :: "n"(N) : "memory");
}

// =================================================================
// fp32 -> bf16 convert (vectorized, one float4 per thread)
// =================================================================
__global__ __launch_bounds__(256) void cvt_kernel(
    const float* __restrict__ src, __nv_bfloat16* __restrict__ dst, int n4)
{
    int i = blockIdx.x * blockDim.x + threadIdx.x;
    if (i < n4) {
        float4 v = reinterpret_cast<const float4*>(src)[i];
        reinterpret_cast<uint2*>(dst)[i] =
            make_uint2(pack_bf16(v.x, v.y), pack_bf16(v.z, v.w));
    }
}

// =================================================================
// Projection: Y = ReLU6(X @ W^T + bias) * scale, all-bf16 GEMM
// 128x128 tile, BK=32, 256 threads, cp.async double buffered
// =================================================================
#define PJS 40
#define PJ_BUF (128 * PJS)
__global__ __launch_bounds__(256, 2) void proj_kernel(
    const __nv_bfloat16* __restrict__ X, const __nv_bfloat16* __restrict__ W,
    const float* __restrict__ bias, __nv_bfloat16* __restrict__ Y, float scale)
{
    __shared__ __align__(16) uint16_t As[2 * PJ_BUF];
    __shared__ __align__(16) uint16_t Bs[2 * PJ_BUF];

    const int tid = threadIdx.x;
    const int lane = tid & 31;
    const int wid = tid >> 5;
    const int g = lane >> 2;
    const int t = lane & 3;
    const int wm = (wid >> 2) * 64;
    const int wn = (wid & 3) * 32;
    const int m0 = blockIdx.y * 128;
    const int n0 = blockIdx.x * 128;

    const int lrow = tid >> 2;          // 0..63? no: tid>>2 = 0..63  (need 0..127)
    // loader mapping: f = tid + i*256, row = f>>2 (0..127), dc = (f&3)*8
    float acc[4][4][4];
#pragma unroll
    for (int mt = 0; mt < 4; mt++)
#pragma unroll
        for (int nt = 0; nt < 4; nt++)
#pragma unroll
            for (int j = 0; j < 4; j++) acc[mt][nt][j] = 0.f;

    // prologue: stage k0=0 into buffer 0
#pragma unroll
    for (int i = 0; i < 2; i++) {
        int f = tid + i * 256;
        int row = f >> 2;
        int dc = (f & 3) * 8;
        cp16(smem_u32(&As[row * PJS + dc]), X + (size_t)(m0 + row) * HID + dc);
        cp16(smem_u32(&Bs[row * PJS + dc]), W + (size_t)(n0 + row) * HID + dc);
    }
    cp_commit();

    for (int it = 0; it < 32; it++) {
        const int b = it & 1;
        if (it < 31) {
            const int k0 = (it + 1) * 32;
            const int ob = (b ^ 1) * PJ_BUF;
#pragma unroll
            for (int i = 0; i < 2; i++) {
                int f = tid + i * 256;
                int row = f >> 2;
                int dc = (f & 3) * 8;
                cp16(smem_u32(&As[ob + row * PJS + dc]),
                     X + (size_t)(m0 + row) * HID + k0 + dc);
                cp16(smem_u32(&Bs[ob + row * PJS + dc]),
                     W + (size_t)(n0 + row) * HID + k0 + dc);
            }
            cp_commit();
            cp_wait<1>();
        } else {
            cp_wait<0>();
        }
        __syncthreads();

        const uint16_t* Ab = As + b * PJ_BUF;
        const uint16_t* Bb = Bs + b * PJ_BUF;
#pragma unroll
        for (int kt = 0; kt < 2; kt++) {
            uint32_t af[4][4], bf[4][2];
#pragma unroll
            for (int mt = 0; mt < 4; mt++)
                ldsm_x4(af[mt][0], af[mt][1], af[mt][2], af[mt][3],
                        smem_u32(&Ab[(wm + mt * 16 + (lane & 15)) * PJS +
                                     kt * 16 + (lane >> 4) * 8]));
#pragma unroll
            for (int ntp = 0; ntp < 2; ntp++) {
                uint32_t r0, r1, r2, r3;
                ldsm_x4(r0, r1, r2, r3,
                        smem_u32(&Bb[(wn + ntp * 16 + (lane & 7) + (lane >> 4) * 8) * PJS +
                                     kt * 16 + ((lane >> 3) & 1) * 8]));
                bf[2 * ntp][0] = r0; bf[2 * ntp][1] = r1;
                bf[2 * ntp + 1][0] = r2; bf[2 * ntp + 1][1] = r3;
            }
#pragma unroll
            for (int mt = 0; mt < 4; mt++)
#pragma unroll
                for (int nt = 0; nt < 4; nt++)
                    mma_bf16(acc[mt][nt], af[mt], bf[nt]);
        }
        __syncthreads();
    }

    // epilogue: bias + relu6 + scale -> bf16
#pragma unroll
    for (int nt = 0; nt < 4; nt++) {
        int col = n0 + wn + nt * 8 + 2 * t;
        float b0 = bias[col], b1 = bias[col + 1];
#pragma unroll
        for (int mt = 0; mt < 4; mt++) {
            int r0 = m0 + wm + mt * 16 + g;
            float o0 = fminf(fmaxf(acc[mt][nt][0] + b0, 0.f), 6.f) * scale;
            float o1 = fminf(fmaxf(acc[mt][nt][1] + b1, 0.f), 6.f) * scale;
            float o2 = fminf(fmaxf(acc[mt][nt][2] + b0, 0.f), 6.f) * scale;
            float o3 = fminf(fmaxf(acc[mt][nt][3] + b1, 0.f), 6.f) * scale;
            *reinterpret_cast<uint32_t*>(Y + (size_t)r0 * HID + col) = pack_bf16(o0, o1);
            *reinterpret_cast<uint32_t*>(Y + (size_t)(r0 + 8) * HID + col) = pack_bf16(o2, o3);
        }
    }
}

// =================================================================
// Flash attention, bf16 MMA. Q pre-scaled by log2e/8 -> ex2 softmax.
// Row-sum via ones-column in V (col 64). Vote-skip O rescale.
// =================================================================
#define AKS 72
#define QS_OFF 0
#define KB_OFF (128 * AKS * 2)
#define VB_OFF (KB_OFF + 2 * 64 * AKS * 2)
#define ATT_SMEM (VB_OFF + 2 * 64 * AKS * 2)   // 55296

__global__ __launch_bounds__(256, 2) void attn_kernel(
    const __nv_bfloat16* __restrict__ qh, const __nv_bfloat16* __restrict__ kh,
    const __nv_bfloat16* __restrict__ vh, float* __restrict__ out)
{
    extern __shared__ __align__(16) char sm[];
    uint16_t* QS = reinterpret_cast<uint16_t*>(sm + QS_OFF);   // [128][AKS]
    uint16_t* KB = reinterpret_cast<uint16_t*>(sm + KB_OFF);   // [2][64][AKS]
    uint16_t* VB = reinterpret_cast<uint16_t*>(sm + VB_OFF);   // [2][64][AKS]

    const int tid = threadIdx.x;
    const int lane = tid & 31;
    const int wid = tid >> 5;
    const int g = lane >> 2;
    const int t = lane & 3;
    const int b = blockIdx.z, h = blockIdx.y;
    const int q0 = blockIdx.x * 128;
    const size_t hoff = (size_t)b * HID + (size_t)h * DH;
    const int wrow = wid * 16;

    // ---- stage Q + K/V tile 0 ----
#pragma unroll
    for (int i = 0; i < 4; i++) {
        int f = tid + i * 256;
        int row = f >> 3;
        int dc = (f & 7) * 8;
        cp16(smem_u32(&QS[row * AKS + dc]),
             qh + (size_t)(q0 + row) * ROWSTR + hoff + dc);
    }
#pragma unroll
    for (int i = 0; i < 2; i++) {
        int f = tid + i * 256;
        int row = f >> 3;
        int dc = (f & 7) * 8;
        cp16(smem_u32(&KB[row * AKS + dc]), kh + (size_t)row * ROWSTR + hoff + dc);
        cp16(smem_u32(&VB[row * AKS + dc]), vh + (size_t)row * ROWSTR + hoff + dc);
    }
    cp_commit();

    // ---- V padding columns: col 64 = 1.0 (bf16), 65..71 = 0, both buffers ----
    for (int i = tid; i < 2 * 64 * 8; i += 256) {
        int bufrow = i >> 3;
        int c = i & 7;
        VB[bufrow * AKS + 64 + c] = (c == 0) ? (uint16_t)0x3F80 : (uint16_t)0;
    }

    cp_wait<0>();
    __syncthreads();

    // ---- persistent Q fragments ----
    uint32_t qa[4][4];
#pragma unroll
    for (int kt = 0; kt < 4; kt++)
        ldsm_x4(qa[kt][0], qa[kt][1], qa[kt][2], qa[kt][3],
                smem_u32(&QS[(wrow + (lane & 15)) * AKS + kt * 16 + (lane >> 4) * 8]));

    float O[8][4], Oex[4];
#pragma unroll
    for (int nt = 0; nt < 8; nt++)
#pragma unroll
        for (int j = 0; j < 4; j++) O[nt][j] = 0.f;
#pragma unroll
    for (int j = 0; j < 4; j++) Oex[j] = 0.f;
    float m0r = -1e30f, m1r = -1e30f;

    for (int it = 0; it < TSEQ / 64; it++) {
        const int cur = it & 1;
        uint16_t* Kc = KB + cur * 64 * AKS;
        uint16_t* Vc = VB + cur * 64 * AKS;

        if (it < TSEQ / 64 - 1) {
            int s0n = (it + 1) * 64;
            uint16_t* Kn = KB + (cur ^ 1) * 64 * AKS;
            uint16_t* Vn = VB + (cur ^ 1) * 64 * AKS;
#pragma unroll
            for (int i = 0; i < 2; i++) {
                int f = tid + i * 256;
                int row = f >> 3;
                int dc = (f & 7) * 8;
                cp16(smem_u32(&Kn[row * AKS + dc]),
                     kh + (size_t)(s0n + row) * ROWSTR + hoff + dc);
                cp16(smem_u32(&Vn[row * AKS + dc]),
                     vh + (size_t)(s0n + row) * ROWSTR + hoff + dc);
            }
            cp_commit();
            cp_wait<1>();
        } else {
            cp_wait<0>();
        }
        __syncthreads();

        // ---- S = Q K^T (log2-domain scores) ----
        float sacc[8][4];
#pragma unroll
        for (int nt = 0; nt < 8; nt++)
#pragma unroll
            for (int j = 0; j < 4; j++) sacc[nt][j] = 0.f;
#pragma unroll
        for (int ntp = 0; ntp < 4; ntp++) {
#pragma unroll
            for (int kt = 0; kt < 4; kt++) {
                uint32_t r0, r1, r2, r3;
                ldsm_x4(r0, r1, r2, r3,
                        smem_u32(&Kc[((lane & 7) + (lane >> 4) * 8 + ntp * 16) * AKS +
                                     kt * 16 + ((lane >> 3) & 1) * 8]));
                uint32_t blo[2] = {r0, r1}, bhi[2] = {r2, r3};
                mma_bf16(sacc[2 * ntp], qa[kt], blo);
                mma_bf16(sacc[2 * ntp + 1], qa[kt], bhi);
            }
        }

        // ---- online softmax (ex2 domain) ----
        float mx0 = -1e30f, mx1 = -1e30f;
#pragma unroll
        for (int nt = 0; nt < 8; nt++) {
            mx0 = fmaxf(mx0, fmaxf(sacc[nt][0], sacc[nt][1]));
            mx1 = fmaxf(mx1, fmaxf(sacc[nt][2], sacc[nt][3]));
        }
        mx0 = fmaxf(mx0, __shfl_xor_sync(0xffffffff, mx0, 1));
        mx0 = fmaxf(mx0, __shfl_xor_sync(0xffffffff, mx0, 2));
        mx1 = fmaxf(mx1, __shfl_xor_sync(0xffffffff, mx1, 1));
        mx1 = fmaxf(mx1, __shfl_xor_sync(0xffffffff, mx1, 2));

        const float mn0 = fmaxf(m0r, mx0), mn1 = fmaxf(m1r, mx1);
        bool upd = (mn0 > m0r) || (mn1 > m1r);
        if (__any_sync(0xffffffffu, upd)) {
            float f0 = ex2(m0r - mn0), f1 = ex2(m1r - mn1);
            m0r = mn0; m1r = mn1;
#pragma unroll
            for (int nt = 0; nt < 8; nt++) {
                O[nt][0] *= f0; O[nt][1] *= f0;
                O[nt][2] *= f1; O[nt][3] *= f1;
            }
            Oex[0] *= f0; Oex[1] *= f0; Oex[2] *= f1; Oex[3] *= f1;
        }

        uint32_t pa[4][4];
#pragma unroll
        for (int nt = 0; nt < 8; nt++) {
            float p0 = ex2(sacc[nt][0] - mn0);
            float p1 = ex2(sacc[nt][1] - mn0);
            float p2 = ex2(sacc[nt][2] - mn1);
            float p3 = ex2(sacc[nt][3] - mn1);
            int kt = nt >> 1;
            if ((nt & 1) == 0) {
                pa[kt][0] = pack_bf16(p0, p1);
                pa[kt][1] = pack_bf16(p2, p3);
            } else {
                pa[kt][2] = pack_bf16(p0, p1);
                pa[kt][3] = pack_bf16(p2, p3);
            }
        }

        // ---- O += P V  (+ ones-column row sums) ----
#pragma unroll
        for (int ntp = 0; ntp < 4; ntp++) {
#pragma unroll
            for (int kt = 0; kt < 4; kt++) {
                uint32_t r0, r1, r2, r3;
                ldsm_x4t(r0, r1, r2, r3,
                         smem_u32(&Vc[((lane & 7) + ((lane >> 3) & 1) * 8 + kt * 16) * AKS +
                                      ntp * 16 + (lane >> 4) * 8]));
                uint32_t blo[2] = {r0, r1}, bhi[2] = {r2, r3};
                mma_bf16(O[2 * ntp], pa[kt], blo);
                mma_bf16(O[2 * ntp + 1], pa[kt], bhi);
            }
        }
#pragma unroll
        for (int kt = 0; kt < 4; kt++) {
            uint32_t r0, r1;
            ldsm_x2t(r0, r1,
                     smem_u32(&Vc[((lane & 7) + ((lane >> 3) & 1) * 8 + kt * 16) * AKS + 64]));
            uint32_t bx[2] = {r0, r1};
            mma_bf16(Oex, pa[kt], bx);
        }
        __syncthreads();
    }

    // ---- epilogue: get row sums from quad leader, normalize, store ----
    const int qlead = lane & ~3;
    float l0 = __shfl_sync(0xffffffff, Oex[0], qlead);
    float l1 = __shfl_sync(0xffffffff, Oex[2], qlead);
    float il0 = 1.f / l0, il1 = 1.f / l1;
    const int gr0 = q0 + wrow + g, gr1 = gr0 + 8;
#pragma unroll
    for (int nt = 0; nt < 8; nt++) {
        int col = nt * 8 + 2 * t;
        float2 o0 = {O[nt][0] * il0, O[nt][1] * il0};
        float2 o1 = {O[nt][2] * il1, O[nt][3] * il1};
        *reinterpret_cast<float2*>(out + (size_t)gr0 * ROWSTR + hoff + col) = o0;
        *reinterpret_cast<float2*>(out + (size_t)gr1 * ROWSTR + hoff + col) = o1;
    }
}

// =================================================================
extern "C" void kernel_launch(void* const* d_in, const int* in_sizes, int n_in,
                              void* d_out, int out_size)
{
    const float* q  = (const float*)d_in[0];
    const float* k  = (const float*)d_in[1];
    const float* v  = (const float*)d_in[2];
    const float* Wq = (const float*)d_in[3];
    const float* bq = (const float*)d_in[4];
    const float* Wk = (const float*)d_in[5];
    const float* bk = (const float*)d_in[6];
    const float* Wv = (const float*)d_in[7];
    const float* bv = (const float*)d_in[8];
    float* out = (float*)d_out;

    __nv_bfloat16 *qh, *kh, *vh, *xq, *xk, *xv, *wq, *wk, *wv;
    cudaGetSymbolAddress((void**)&qh, g_qh);
    cudaGetSymbolAddress((void**)&kh, g_kh);
    cudaGetSymbolAddress((void**)&vh, g_vh);
    cudaGetSymbolAddress((void**)&xq, g_xq);
    cudaGetSymbolAddress((void**)&xk, g_xk);
    cudaGetSymbolAddress((void**)&xv, g_xv);
    cudaGetSymbolAddress((void**)&wq, g_wq);
    cudaGetSymbolAddress((void**)&wk, g_wk);
    cudaGetSymbolAddress((void**)&wv, g_wv);

    const int n4i = MR * HID / 4;     // 2M float4 per input
    const int n4w = HID * HID / 4;    // 256K per weight
    cvt_kernel<<<n4i / 256, 256>>>(q, xq, n4i);
    cvt_kernel<<<n4i / 256, 256>>>(k, xk, n4i);
    cvt_kernel<<<n4i / 256, 256>>>(v, xv, n4i);
    cvt_kernel<<<n4w / 256, 256>>>(Wq, wq, n4w);
    cvt_kernel<<<n4w / 256, 256>>>(Wk, wk, n4w);
    cvt_kernel<<<n4w / 256, 256>>>(Wv, wv, n4w);

    dim3 pg(HID / 128, MR / 128);
    proj_kernel<<<pg, 256>>>(xq, wq, bq, qh, 0.125f * LOG2E);  // log2e/sqrt(d) folded
    proj_kernel<<<pg, 256>>>(xk, wk, bk, kh, 1.0f);
    proj_kernel<<<pg, 256>>>(xv, wv, bv, vh, 1.0f);

    cudaFuncSetAttribute(attn_kernel,
                         cudaFuncAttributeMaxDynamicSharedMemorySize, ATT_SMEM);
    dim3 ag(TT / 128, NH, BB);
    attn_kernel<<<ag, 256, ATT_SMEM>>>(qh, kh, vh, out);
}

// round 6
// speedup vs baseline: 7.5525x; 1.1599x over previous
#include <cuda_runtime.h>
#include <cuda_bf16.h>
#include <cstdint>

#define HID 1024
#define NH 16
#define DH 64
#define TT 2048
#define TSEQ 2048
#define BB 4
#define MR (TT*BB)          // 8192 rows for projections
#define ROWSTR (BB*HID)     // 4096 elements per t-step
#define LOG2E 1.4426950408889634f

// ---------------- scratch ----------------
__device__ __nv_bfloat16 g_qh[(size_t)MR * HID];
__device__ __nv_bfloat16 g_kh[(size_t)MR * HID];
__device__ __nv_bfloat16 g_vh[(size_t)MR * HID];
__device__ __nv_bfloat16 g_xq[(size_t)MR * HID];
__device__ __nv_bfloat16 g_xk[(size_t)MR * HID];
__device__ __nv_bfloat16 g_xv[(size_t)MR * HID];
__device__ __nv_bfloat16 g_wq[(size_t)HID * HID];
__device__ __nv_bfloat16 g_wk[(size_t)HID * HID];
__device__ __nv_bfloat16 g_wv[(size_t)HID * HID];

// ---------------- helpers ----------------
__device__ __forceinline__ uint32_t pack_bf16(float lo, float hi) {
    uint32_t d;
    asm("cvt.rn.bf16x2.f32 %0, %1, %2;" : "=r"(d) : "f"(hi), "f"(lo));
    return d;
}
__device__ __forceinline__ float ex2(float x) {
    float r; asm("ex2.approx.f32 %0, %1;" : "=f"(r) : "f"(x)); return r;
}
__device__ __forceinline__ uint32_t smem_u32(const void* p) {
    return (uint32_t)__cvta_generic_to_shared(p);
}
__device__ __forceinline__ void ldsm_x4(uint32_t& r0, uint32_t& r1,
                                        uint32_t& r2, uint32_t& r3, uint32_t a) {
    asm volatile("ldmatrix.sync.aligned.m8n8.x4.shared.b16 {%0,%1,%2,%3}, [%4];"
                 : "=r"(r0), "=r"(r1), "=r"(r2), "=r"(r3) : "r"(a));
}
__device__ __forceinline__ void ldsm_x4t(uint32_t& r0, uint32_t& r1,
                                         uint32_t& r2, uint32_t& r3, uint32_t a) {
    asm volatile("ldmatrix.sync.aligned.m8n8.x4.trans.shared.b16 {%0,%1,%2,%3}, [%4];"
                 : "=r"(r0), "=r"(r1), "=r"(r2), "=r"(r3) : "r"(a));
}
__device__ __forceinline__ void ldsm_x2t(uint32_t& r0, uint32_t& r1, uint32_t a) {
    asm volatile("ldmatrix.sync.aligned.m8n8.x2.trans.shared.b16 {%0,%1}, [%2];"
                 : "=r"(r0), "=r"(r1) : "r"(a));
}
__device__ __forceinline__ void mma_bf16(float* c, const uint32_t* a, const uint32_t* b) {
    asm volatile(
        "mma.sync.aligned.m16n8k16.row.col.f32.bf16.bf16.f32 "
        "{%0,%1,%2,%3}, {%4,%5,%6,%7}, {%8,%9}, {%0,%1,%2,%3};"
        : "+f"(c[0]), "+f"(c[1]), "+f"(c[2]), "+f"(c[3])
        : "r"(a[0]), "r"(a[1]), "r"(a[2]), "r"(a[3]), "r"(b[0]), "r"(b[1]));
}
__device__ __forceinline__ void cp16(uint32_t dst, const void* src) {
    asm volatile("cp.async.cg.shared.global [%0], [%1], 16;" :: "r"(dst), "l"(src) : "memory");
}
__device__ __forceinline__ void cp_commit() {
    asm volatile("cp.async.commit_group;" ::: "memory");
}
template <int N> __device__ __forceinline__ void cp_wait() {
    asm volatile("cp.async.wait_group %0;" :: "n"(N) : "memory");
}

// =================================================================
// fp32 -> bf16 convert, 3 arrays per launch (y-indexed)
// =================================================================
__global__ __launch_bounds__(256) void cvt3_kernel(
    const float* __restrict__ s0, const float* __restrict__ s1,
    const float* __restrict__ s2, __nv_bfloat16* __restrict__ d0,
    __nv_bfloat16* __restrict__ d1, __nv_bfloat16* __restrict__ d2, int n4)
{
    const float* src = (blockIdx.y == 0) ? s0 : (blockIdx.y == 1) ? s1 : s2;
    __nv_bfloat16* dst = (blockIdx.y == 0) ? d0 : (blockIdx.y == 1) ? d1 : d2;
    int i = blockIdx.x * blockDim.x + threadIdx.x;
    if (i < n4) {
        float4 v = reinterpret_cast<const float4*>(src)[i];
        reinterpret_cast<uint2*>(dst)[i] =
            make_uint2(pack_bf16(v.x, v.y), pack_bf16(v.z, v.w));
    }
}

// =================================================================
// Projection: Y = ReLU6(X @ W^T + bias) * scale, all-bf16 mma.sync
// 128x128 tile, BK=64, 256 threads, cp.async double buffered,
// single barrier per k-iter, one launch for all 3 projections (z).
// =================================================================
#define PJS 72
#define PJ_TILE (128 * PJS)                    // bf16 elems per matrix tile
#define PJ_STAGE (2 * PJ_TILE)                 // A + B
#define PJ_SMEM (2 * PJ_STAGE * 2)             // bytes: 2 stages

__global__ __launch_bounds__(256, 2) void proj_kernel(
    const __nv_bfloat16* __restrict__ Xq, const __nv_bfloat16* __restrict__ Wq,
    const float* __restrict__ bq, __nv_bfloat16* __restrict__ Yq,
    const __nv_bfloat16* __restrict__ Xk, const __nv_bfloat16* __restrict__ Wk,
    const float* __restrict__ bk, __nv_bfloat16* __restrict__ Yk,
    const __nv_bfloat16* __restrict__ Xv, const __nv_bfloat16* __restrict__ Wv,
    const float* __restrict__ bv, __nv_bfloat16* __restrict__ Yv,
    float sq)
{
    extern __shared__ __align__(16) uint16_t psm[];   // [2][A|B]

    const int tid = threadIdx.x;
    const int lane = tid & 31;
    const int wid = tid >> 5;
    const int g = lane >> 2;
    const int t = lane & 3;
    const int wm = (wid >> 2) * 64;
    const int wn = (wid & 3) * 32;
    const int z = blockIdx.z;
    const int m0 = blockIdx.y * 128;
    const int n0 = blockIdx.x * 128;

    const __nv_bfloat16* X = (z == 0) ? Xq : (z == 1) ? Xk : Xv;
    const __nv_bfloat16* W = (z == 0) ? Wq : (z == 1) ? Wk : Wv;
    const float*      bias = (z == 0) ? bq : (z == 1) ? bk : bv;
    __nv_bfloat16*       Y = (z == 0) ? Yq : (z == 1) ? Yk : Yv;
    const float      scale = (z == 0) ? sq : 1.0f;

    float acc[4][4][4];
#pragma unroll
    for (int mt = 0; mt < 4; mt++)
#pragma unroll
        for (int nt = 0; nt < 4; nt++)
#pragma unroll
            for (int j = 0; j < 4; j++) acc[mt][nt][j] = 0.f;

    // loader mapping: f = tid + i*256 (i<4) -> row = f>>3, chunk = f&7
    auto fill = [&](int s, int k0) {
        uint16_t* As = psm + s * PJ_STAGE;
        uint16_t* Bs = As + PJ_TILE;
#pragma unroll
        for (int i = 0; i < 4; i++) {
            int f = tid + i * 256;
            int row = f >> 3;
            int dc = (f & 7) * 8;
            cp16(smem_u32(&As[row * PJS + dc]),
                 X + (size_t)(m0 + row) * HID + k0 + dc);
            cp16(smem_u32(&Bs[row * PJS + dc]),
                 W + (size_t)(n0 + row) * HID + k0 + dc);
        }
        cp_commit();
    };

    fill(0, 0);

    for (int it = 0; it < 16; it++) {
        cp_wait<0>();
        __syncthreads();
        if (it < 15) fill((it + 1) & 1, (it + 1) * 64);

        const uint16_t* Ab = psm + (it & 1) * PJ_STAGE;
        const uint16_t* Bb = Ab + PJ_TILE;
#pragma unroll
        for (int kt = 0; kt < 4; kt++) {
            uint32_t af[4][4], bf[4][2];
#pragma unroll
            for (int mt = 0; mt < 4; mt++)
                ldsm_x4(af[mt][0], af[mt][1], af[mt][2], af[mt][3],
                        smem_u32(&Ab[(wm + mt * 16 + (lane & 15)) * PJS +
                                     kt * 16 + (lane >> 4) * 8]));
#pragma unroll
            for (int ntp = 0; ntp < 2; ntp++) {
                uint32_t r0, r1, r2, r3;
                ldsm_x4(r0, r1, r2, r3,
                        smem_u32(&Bb[(wn + ntp * 16 + (lane & 7) + (lane >> 4) * 8) * PJS +
                                     kt * 16 + ((lane >> 3) & 1) * 8]));
                bf[2 * ntp][0] = r0; bf[2 * ntp][1] = r1;
                bf[2 * ntp + 1][0] = r2; bf[2 * ntp + 1][1] = r3;
            }
#pragma unroll
            for (int mt = 0; mt < 4; mt++)
#pragma unroll
                for (int nt = 0; nt < 4; nt++)
                    mma_bf16(acc[mt][nt], af[mt], bf[nt]);
        }
    }

    // epilogue: bias + relu6 + scale -> bf16
#pragma unroll
    for (int nt = 0; nt < 4; nt++) {
        int col = n0 + wn + nt * 8 + 2 * t;
        float b0 = bias[col], b1 = bias[col + 1];
#pragma unroll
        for (int mt = 0; mt < 4; mt++) {
            int r0 = m0 + wm + mt * 16 + g;
            float o0 = fminf(fmaxf(acc[mt][nt][0] + b0, 0.f), 6.f) * scale;
            float o1 = fminf(fmaxf(acc[mt][nt][1] + b1, 0.f), 6.f) * scale;
            float o2 = fminf(fmaxf(acc[mt][nt][2] + b0, 0.f), 6.f) * scale;
            float o3 = fminf(fmaxf(acc[mt][nt][3] + b1, 0.f), 6.f) * scale;
            *reinterpret_cast<uint32_t*>(Y + (size_t)r0 * HID + col) = pack_bf16(o0, o1);
            *reinterpret_cast<uint32_t*>(Y + (size_t)(r0 + 8) * HID + col) = pack_bf16(o2, o3);
        }
    }
}

// =================================================================
// Flash attention, bf16 MMA. Q pre-scaled by log2e/8 -> ex2 softmax.
// Row-sum via ones-column in V (col 64). Vote-skip O rescale.
// Single barrier per KV tile (prefetch after the barrier).
// =================================================================
#define AKS 72
#define QS_OFF 0
#define KB_OFF (128 * AKS * 2)
#define VB_OFF (KB_OFF + 2 * 64 * AKS * 2)
#define ATT_SMEM (VB_OFF + 2 * 64 * AKS * 2)   // 55296

__global__ __launch_bounds__(256, 2) void attn_kernel(
    const __nv_bfloat16* __restrict__ qh, const __nv_bfloat16* __restrict__ kh,
    const __nv_bfloat16* __restrict__ vh, float* __restrict__ out)
{
    extern __shared__ __align__(16) char sm[];
    uint16_t* QS = reinterpret_cast<uint16_t*>(sm + QS_OFF);
    uint16_t* KB = reinterpret_cast<uint16_t*>(sm + KB_OFF);
    uint16_t* VB = reinterpret_cast<uint16_t*>(sm + VB_OFF);

    const int tid = threadIdx.x;
    const int lane = tid & 31;
    const int wid = tid >> 5;
    const int g = lane >> 2;
    const int t = lane & 3;
    const int b = blockIdx.z, h = blockIdx.y;
    const int q0 = blockIdx.x * 128;
    const size_t hoff = (size_t)b * HID + (size_t)h * DH;
    const int wrow = wid * 16;

    // ---- stage Q + K/V tile 0 (one commit group) ----
#pragma unroll
    for (int i = 0; i < 4; i++) {
        int f = tid + i * 256;
        int row = f >> 3;
        int dc = (f & 7) * 8;
        cp16(smem_u32(&QS[row * AKS + dc]),
             qh + (size_t)(q0 + row) * ROWSTR + hoff + dc);
    }
#pragma unroll
    for (int i = 0; i < 2; i++) {
        int f = tid + i * 256;
        int row = f >> 3;
        int dc = (f & 7) * 8;
        cp16(smem_u32(&KB[row * AKS + dc]), kh + (size_t)row * ROWSTR + hoff + dc);
        cp16(smem_u32(&VB[row * AKS + dc]), vh + (size_t)row * ROWSTR + hoff + dc);
    }
    cp_commit();

    // V padding cols: col 64 = 1.0 bf16, 65..71 = 0, both buffers
    for (int i = tid; i < 2 * 64 * 8; i += 256) {
        int bufrow = i >> 3;
        int c = i & 7;
        VB[bufrow * AKS + 64 + c] = (c == 0) ? (uint16_t)0x3F80 : (uint16_t)0;
    }

    cp_wait<0>();
    __syncthreads();

    // ---- persistent Q fragments ----
    uint32_t qa[4][4];
#pragma unroll
    for (int kt = 0; kt < 4; kt++)
        ldsm_x4(qa[kt][0], qa[kt][1], qa[kt][2], qa[kt][3],
                smem_u32(&QS[(wrow + (lane & 15)) * AKS + kt * 16 + (lane >> 4) * 8]));

    float O[8][4], Oex[4];
#pragma unroll
    for (int nt = 0; nt < 8; nt++)
#pragma unroll
        for (int j = 0; j < 4; j++) O[nt][j] = 0.f;
#pragma unroll
    for (int j = 0; j < 4; j++) Oex[j] = 0.f;
    float m0r = -1e30f, m1r = -1e30f;

    for (int it = 0; it < TSEQ / 64; it++) {
        const int cur = it & 1;
        uint16_t* Kc = KB + cur * 64 * AKS;
        uint16_t* Vc = VB + cur * 64 * AKS;

        if (it > 0) {
            cp_wait<0>();
            __syncthreads();
        }
        // prefetch next tile AFTER the barrier (buffer proven drained)
        if (it < TSEQ / 64 - 1) {
            int s0n = (it + 1) * 64;
            uint16_t* Kn = KB + (cur ^ 1) * 64 * AKS;
            uint16_t* Vn = VB + (cur ^ 1) * 64 * AKS;
#pragma unroll
            for (int i = 0; i < 2; i++) {
                int f = tid + i * 256;
                int row = f >> 3;
                int dc = (f & 7) * 8;
                cp16(smem_u32(&Kn[row * AKS + dc]),
                     kh + (size_t)(s0n + row) * ROWSTR + hoff + dc);
                cp16(smem_u32(&Vn[row * AKS + dc]),
                     vh + (size_t)(s0n + row) * ROWSTR + hoff + dc);
            }
            cp_commit();
        }

        // ---- S = Q K^T (log2-domain scores) ----
        float sacc[8][4];
#pragma unroll
        for (int nt = 0; nt < 8; nt++)
#pragma unroll
            for (int j = 0; j < 4; j++) sacc[nt][j] = 0.f;
#pragma unroll
        for (int ntp = 0; ntp < 4; ntp++) {
#pragma unroll
            for (int kt = 0; kt < 4; kt++) {
                uint32_t r0, r1, r2, r3;
                ldsm_x4(r0, r1, r2, r3,
                        smem_u32(&Kc[((lane & 7) + (lane >> 4) * 8 + ntp * 16) * AKS +
                                     kt * 16 + ((lane >> 3) & 1) * 8]));
                uint32_t blo[2] = {r0, r1}, bhi[2] = {r2, r3};
                mma_bf16(sacc[2 * ntp], qa[kt], blo);
                mma_bf16(sacc[2 * ntp + 1], qa[kt], bhi);
            }
        }

        // ---- online softmax (ex2 domain) ----
        float mx0 = -1e30f, mx1 = -1e30f;
#pragma unroll
        for (int nt = 0; nt < 8; nt++) {
            mx0 = fmaxf(mx0, fmaxf(sacc[nt][0], sacc[nt][1]));
            mx1 = fmaxf(mx1, fmaxf(sacc[nt][2], sacc[nt][3]));
        }
        mx0 = fmaxf(mx0, __shfl_xor_sync(0xffffffff, mx0, 1));
        mx0 = fmaxf(mx0, __shfl_xor_sync(0xffffffff, mx0, 2));
        mx1 = fmaxf(mx1, __shfl_xor_sync(0xffffffff, mx1, 1));
        mx1 = fmaxf(mx1, __shfl_xor_sync(0xffffffff, mx1, 2));

        const float mn0 = fmaxf(m0r, mx0), mn1 = fmaxf(m1r, mx1);
        bool upd = (mn0 > m0r) || (mn1 > m1r);
        if (__any_sync(0xffffffffu, upd)) {
            float f0 = ex2(m0r - mn0), f1 = ex2(m1r - mn1);
            m0r = mn0; m1r = mn1;
#pragma unroll
            for (int nt = 0; nt < 8; nt++) {
                O[nt][0] *= f0; O[nt][1] *= f0;
                O[nt][2] *= f1; O[nt][3] *= f1;
            }
            Oex[0] *= f0; Oex[1] *= f0; Oex[2] *= f1; Oex[3] *= f1;
        }

        uint32_t pa[4][4];
#pragma unroll
        for (int nt = 0; nt < 8; nt++) {
            float p0 = ex2(sacc[nt][0] - mn0);
            float p1 = ex2(sacc[nt][1] - mn0);
            float p2 = ex2(sacc[nt][2] - mn1);
            float p3 = ex2(sacc[nt][3] - mn1);
            int kt = nt >> 1;
            if ((nt & 1) == 0) {
                pa[kt][0] = pack_bf16(p0, p1);
                pa[kt][1] = pack_bf16(p2, p3);
            } else {
                pa[kt][2] = pack_bf16(p0, p1);
                pa[kt][3] = pack_bf16(p2, p3);
            }
        }

        // ---- O += P V  (+ ones-column row sums) ----
#pragma unroll
        for (int ntp = 0; ntp < 4; ntp++) {
#pragma unroll
            for (int kt = 0; kt < 4; kt++) {
                uint32_t r0, r1, r2, r3;
                ldsm_x4t(r0, r1, r2, r3,
                         smem_u32(&Vc[((lane & 7) + ((lane >> 3) & 1) * 8 + kt * 16) * AKS +
                                      ntp * 16 + (lane >> 4) * 8]));
                uint32_t blo[2] = {r0, r1}, bhi[2] = {r2, r3};
                mma_bf16(O[2 * ntp], pa[kt], blo);
                mma_bf16(O[2 * ntp + 1], pa[kt], bhi);
            }
        }
#pragma unroll
        for (int kt = 0; kt < 4; kt++) {
            uint32_t r0, r1;
            ldsm_x2t(r0, r1,
                     smem_u32(&Vc[((lane & 7) + ((lane >> 3) & 1) * 8 + kt * 16) * AKS + 64]));
            uint32_t bx[2] = {r0, r1};
            mma_bf16(Oex, pa[kt], bx);
        }
    }

    // ---- epilogue: row sums from quad leader, normalize, store ----
    const int qlead = lane & ~3;
    float l0 = __shfl_sync(0xffffffff, Oex[0], qlead);
    float l1 = __shfl_sync(0xffffffff, Oex[2], qlead);
    float il0 = 1.f / l0, il1 = 1.f / l1;
    const int gr0 = q0 + wrow + g, gr1 = gr0 + 8;
#pragma unroll
    for (int nt = 0; nt < 8; nt++) {
        int col = nt * 8 + 2 * t;
        float2 o0 = {O[nt][0] * il0, O[nt][1] * il0};
        float2 o1 = {O[nt][2] * il1, O[nt][3] * il1};
        *reinterpret_cast<float2*>(out + (size_t)gr0 * ROWSTR + hoff + col) = o0;
        *reinterpret_cast<float2*>(out + (size_t)gr1 * ROWSTR + hoff + col) = o1;
    }
}

// =================================================================
extern "C" void kernel_launch(void* const* d_in, const int* in_sizes, int n_in,
                              void* d_out, int out_size)
{
    const float* q  = (const float*)d_in[0];
    const float* k  = (const float*)d_in[1];
    const float* v  = (const float*)d_in[2];
    const float* Wq = (const float*)d_in[3];
    const float* bq = (const float*)d_in[4];
    const float* Wk = (const float*)d_in[5];
    const float* bk = (const float*)d_in[6];
    const float* Wv = (const float*)d_in[7];
    const float* bv = (const float*)d_in[8];
    float* out = (float*)d_out;

    __nv_bfloat16 *qh, *kh, *vh, *xq, *xk, *xv, *wq, *wk, *wv;
    cudaGetSymbolAddress((void**)&qh, g_qh);
    cudaGetSymbolAddress((void**)&kh, g_kh);
    cudaGetSymbolAddress((void**)&vh, g_vh);
    cudaGetSymbolAddress((void**)&xq, g_xq);
    cudaGetSymbolAddress((void**)&xk, g_xk);
    cudaGetSymbolAddress((void**)&xv, g_xv);
    cudaGetSymbolAddress((void**)&wq, g_wq);
    cudaGetSymbolAddress((void**)&wk, g_wk);
    cudaGetSymbolAddress((void**)&wv, g_wv);

    const int n4i = MR * HID / 4;     // input elements / 4
    const int n4w = HID * HID / 4;
    cvt3_kernel<<<dim3(n4i / 256, 3), 256>>>(q, k, v, xq, xk, xv, n4i);
    cvt3_kernel<<<dim3(n4w / 256, 3), 256>>>(Wq, Wk, Wv, wq, wk, wv, n4w);

    cudaFuncSetAttribute(proj_kernel,
                         cudaFuncAttributeMaxDynamicSharedMemorySize, PJ_SMEM);
    dim3 pg(HID / 128, MR / 128, 3);
    proj_kernel<<<pg, 256, PJ_SMEM>>>(
        xq, wq, bq, qh,
        xk, wk, bk, kh,
        xv, wv, bv, vh,
        0.125f * LOG2E);

    cudaFuncSetAttribute(attn_kernel,
                         cudaFuncAttributeMaxDynamicSharedMemorySize, ATT_SMEM);
    dim3 ag(TT / 128, NH, BB);
    attn_kernel<<<ag, 256, ATT_SMEM>>>(qh, kh, vh, out);
}

// round 7
// speedup vs baseline: 7.7862x; 1.0309x over previous
#include <cuda_runtime.h>
#include <cuda_bf16.h>
#include <cstdint>

#define HID 1024
#define NH 16
#define DH 64
#define TT 2048
#define TSEQ 2048
#define BB 4
#define MR (TT*BB)          // 8192 rows for projections
#define ROWSTR (BB*HID)     // 4096 elements per t-step
#define LOG2E 1.4426950408889634f

// ---------------- scratch ----------------
__device__ __nv_bfloat16 g_qh[(size_t)MR * HID];
__device__ __nv_bfloat16 g_kh[(size_t)MR * HID];
__device__ __nv_bfloat16 g_vh[(size_t)MR * HID];
__device__ __nv_bfloat16 g_xq[(size_t)MR * HID];
__device__ __nv_bfloat16 g_xk[(size_t)MR * HID];
__device__ __nv_bfloat16 g_xv[(size_t)MR * HID];
__device__ __nv_bfloat16 g_wq[(size_t)HID * HID];
__device__ __nv_bfloat16 g_wk[(size_t)HID * HID];
__device__ __nv_bfloat16 g_wv[(size_t)HID * HID];

// ---------------- helpers ----------------
__device__ __forceinline__ uint32_t pack_bf16(float lo, float hi) {
    uint32_t d;
    asm("cvt.rn.bf16x2.f32 %0, %1, %2;" : "=r"(d) : "f"(hi), "f"(lo));
    return d;
}
__device__ __forceinline__ float ex2(float x) {
    float r; asm("ex2.approx.f32 %0, %1;" : "=f"(r) : "f"(x)); return r;
}
__device__ __forceinline__ uint32_t ex2b2(uint32_t x) {
    uint32_t r; asm("ex2.approx.ftz.bf16x2 %0, %1;" : "=r"(r) : "r"(x)); return r;
}
__device__ __forceinline__ uint32_t smem_u32(const void* p) {
    return (uint32_t)__cvta_generic_to_shared(p);
}
__device__ __forceinline__ void ldsm_x4(uint32_t& r0, uint32_t& r1,
                                        uint32_t& r2, uint32_t& r3, uint32_t a) {
    asm volatile("ldmatrix.sync.aligned.m8n8.x4.shared.b16 {%0,%1,%2,%3}, [%4];"
                 : "=r"(r0), "=r"(r1), "=r"(r2), "=r"(r3) : "r"(a));
}
__device__ __forceinline__ void ldsm_x4t(uint32_t& r0, uint32_t& r1,
                                         uint32_t& r2, uint32_t& r3, uint32_t a) {
    asm volatile("ldmatrix.sync.aligned.m8n8.x4.trans.shared.b16 {%0,%1,%2,%3}, [%4];"
                 : "=r"(r0), "=r"(r1), "=r"(r2), "=r"(r3) : "r"(a));
}
__device__ __forceinline__ void ldsm_x2t(uint32_t& r0, uint32_t& r1, uint32_t a) {
    asm volatile("ldmatrix.sync.aligned.m8n8.x2.trans.shared.b16 {%0,%1}, [%2];"
                 : "=r"(r0), "=r"(r1) : "r"(a));
}
__device__ __forceinline__ void mma_bf16(float* c, const uint32_t* a, const uint32_t* b) {
    asm volatile(
        "mma.sync.aligned.m16n8k16.row.col.f32.bf16.bf16.f32 "
        "{%0,%1,%2,%3}, {%4,%5,%6,%7}, {%8,%9}, {%0,%1,%2,%3};"
        : "+f"(c[0]), "+f"(c[1]), "+f"(c[2]), "+f"(c[3])
        : "r"(a[0]), "r"(a[1]), "r"(a[2]), "r"(a[3]), "r"(b[0]), "r"(b[1]));
}
__device__ __forceinline__ void cp16(uint32_t dst, const void* src) {
    asm volatile("cp.async.cg.shared.global [%0], [%1], 16;" :: "r"(dst), "l"(src) : "memory");
}
__device__ __forceinline__ void cp_commit() {
    asm volatile("cp.async.commit_group;" ::: "memory");
}
template <int N> __device__ __forceinline__ void cp_wait() {
    asm volatile("cp.async.wait_group %0;" :: "n"(N) : "memory");
}

// =================================================================
// fp32 -> bf16 convert, 3 arrays per launch (y-indexed)
// =================================================================
__global__ __launch_bounds__(256) void cvt3_kernel(
    const float* __restrict__ s0, const float* __restrict__ s1,
    const float* __restrict__ s2, __nv_bfloat16* __restrict__ d0,
    __nv_bfloat16* __restrict__ d1, __nv_bfloat16* __restrict__ d2, int n4)
{
    const float* src = (blockIdx.y == 0) ? s0 : (blockIdx.y == 1) ? s1 : s2;
    __nv_bfloat16* dst = (blockIdx.y == 0) ? d0 : (blockIdx.y == 1) ? d1 : d2;
    int i = blockIdx.x * blockDim.x + threadIdx.x;
    if (i < n4) {
        float4 v = reinterpret_cast<const float4*>(src)[i];
        reinterpret_cast<uint2*>(dst)[i] =
            make_uint2(pack_bf16(v.x, v.y), pack_bf16(v.z, v.w));
    }
}

// =================================================================
// Projection: Y = ReLU6(X @ W^T + bias) * scale, all-bf16 mma.sync
// 128x128 tile, BK=64, 256 threads, cp.async double buffered,
// single barrier per k-iter, one launch for all 3 projections (z).
// =================================================================
#define PJS 72
#define PJ_TILE (128 * PJS)
#define PJ_STAGE (2 * PJ_TILE)
#define PJ_STAGE_BYTES (PJ_STAGE * 2)
#define PJ_SMEM (2 * PJ_STAGE * 2)

__global__ __launch_bounds__(256, 2) void proj_kernel(
    const __nv_bfloat16* __restrict__ Xq, const __nv_bfloat16* __restrict__ Wq,
    const float* __restrict__ bq, __nv_bfloat16* __restrict__ Yq,
    const __nv_bfloat16* __restrict__ Xk, const __nv_bfloat16* __restrict__ Wk,
    const float* __restrict__ bk, __nv_bfloat16* __restrict__ Yk,
    const __nv_bfloat16* __restrict__ Xv, const __nv_bfloat16* __restrict__ Wv,
    const float* __restrict__ bv, __nv_bfloat16* __restrict__ Yv,
    float sq)
{
    extern __shared__ __align__(16) uint16_t psm[];

    const int tid = threadIdx.x;
    const int lane = tid & 31;
    const int wid = tid >> 5;
    const int g = lane >> 2;
    const int t = lane & 3;
    const int wm = (wid >> 2) * 64;
    const int wn = (wid & 3) * 32;
    const int z = blockIdx.z;
    const int m0 = blockIdx.y * 128;
    const int n0 = blockIdx.x * 128;

    const __nv_bfloat16* X = (z == 0) ? Xq : (z == 1) ? Xk : Xv;
    const __nv_bfloat16* W = (z == 0) ? Wq : (z == 1) ? Wk : Wv;
    const float*      bias = (z == 0) ? bq : (z == 1) ? bk : bv;
    __nv_bfloat16*       Y = (z == 0) ? Yq : (z == 1) ? Yk : Yv;
    const float      scale = (z == 0) ? sq : 1.0f;

    float acc[4][4][4];
#pragma unroll
    for (int mt = 0; mt < 4; mt++)
#pragma unroll
        for (int nt = 0; nt < 4; nt++)
#pragma unroll
            for (int j = 0; j < 4; j++) acc[mt][nt][j] = 0.f;

    // hoisted per-lane ldmatrix bases (bytes from psm)
    const uint32_t smbase = smem_u32(psm);
    const uint32_t abase =
        smbase + ((wm + (lane & 15)) * PJS + (lane >> 4) * 8) * 2;
    const uint32_t bbase =
        smbase + PJ_TILE * 2 +
        ((wn + (lane & 7) + (lane >> 4) * 8) * PJS + ((lane >> 3) & 1) * 8) * 2;

    auto fill = [&](int s, int k0) {
        uint16_t* As = psm + s * PJ_STAGE;
        uint16_t* Bs = As + PJ_TILE;
#pragma unroll
        for (int i = 0; i < 4; i++) {
            int f = tid + i * 256;
            int row = f >> 3;
            int dc = (f & 7) * 8;
            cp16(smem_u32(&As[row * PJS + dc]),
                 X + (size_t)(m0 + row) * HID + k0 + dc);
            cp16(smem_u32(&Bs[row * PJS + dc]),
                 W + (size_t)(n0 + row) * HID + k0 + dc);
        }
        cp_commit();
    };

    fill(0, 0);

    for (int it = 0; it < 16; it++) {
        cp_wait<0>();
        __syncthreads();
        if (it < 15) fill((it + 1) & 1, (it + 1) * 64);

        const uint32_t so = (uint32_t)(it & 1) * PJ_STAGE_BYTES;
        const uint32_t ab = abase + so;
        const uint32_t bb = bbase + so;
#pragma unroll
        for (int kt = 0; kt < 4; kt++) {
            uint32_t af[4][4], bf[4][2];
#pragma unroll
            for (int mt = 0; mt < 4; mt++)
                ldsm_x4(af[mt][0], af[mt][1], af[mt][2], af[mt][3],
                        ab + (mt * 16 * PJS + kt * 16) * 2);
#pragma unroll
            for (int ntp = 0; ntp < 2; ntp++) {
                uint32_t r0, r1, r2, r3;
                ldsm_x4(r0, r1, r2, r3,
                        bb + (ntp * 16 * PJS + kt * 16) * 2);
                bf[2 * ntp][0] = r0; bf[2 * ntp][1] = r1;
                bf[2 * ntp + 1][0] = r2; bf[2 * ntp + 1][1] = r3;
            }
#pragma unroll
            for (int mt = 0; mt < 4; mt++)
#pragma unroll
                for (int nt = 0; nt < 4; nt++)
                    mma_bf16(acc[mt][nt], af[mt], bf[nt]);
        }
    }

    // epilogue: bias + relu6 + scale -> bf16
#pragma unroll
    for (int nt = 0; nt < 4; nt++) {
        int col = n0 + wn + nt * 8 + 2 * t;
        float b0 = bias[col], b1 = bias[col + 1];
#pragma unroll
        for (int mt = 0; mt < 4; mt++) {
            int r0 = m0 + wm + mt * 16 + g;
            float o0 = fminf(fmaxf(acc[mt][nt][0] + b0, 0.f), 6.f) * scale;
            float o1 = fminf(fmaxf(acc[mt][nt][1] + b1, 0.f), 6.f) * scale;
            float o2 = fminf(fmaxf(acc[mt][nt][2] + b0, 0.f), 6.f) * scale;
            float o3 = fminf(fmaxf(acc[mt][nt][3] + b1, 0.f), 6.f) * scale;
            *reinterpret_cast<uint32_t*>(Y + (size_t)r0 * HID + col) = pack_bf16(o0, o1);
            *reinterpret_cast<uint32_t*>(Y + (size_t)(r0 + 8) * HID + col) = pack_bf16(o2, o3);
        }
    }
}

// =================================================================
// Flash attention, bf16 MMA, bf16x2 ex2 softmax (Q pre-scaled by
// log2e/8). Row-sum via ones-column in V (col 64). Vote-skip rescale.
// Single barrier per KV tile; hoisted ldmatrix addressing.
// =================================================================
#define AKS 72
#define QS_OFF 0
#define KB_OFF (128 * AKS * 2)
#define VB_OFF (KB_OFF + 2 * 64 * AKS * 2)
#define KVBYTES (64 * AKS * 2)
#define ATT_SMEM (VB_OFF + 2 * 64 * AKS * 2)   // 55296

__global__ __launch_bounds__(256, 2) void attn_kernel(
    const __nv_bfloat16* __restrict__ qh, const __nv_bfloat16* __restrict__ kh,
    const __nv_bfloat16* __restrict__ vh, float* __restrict__ out)
{
    extern __shared__ __align__(16) char sm[];
    uint16_t* QS = reinterpret_cast<uint16_t*>(sm + QS_OFF);
    uint16_t* KB = reinterpret_cast<uint16_t*>(sm + KB_OFF);
    uint16_t* VB = reinterpret_cast<uint16_t*>(sm + VB_OFF);

    const int tid = threadIdx.x;
    const int lane = tid & 31;
    const int wid = tid >> 5;
    const int g = lane >> 2;
    const int t = lane & 3;
    const int b = blockIdx.z, h = blockIdx.y;
    const int q0 = blockIdx.x * 128;
    const size_t hoff = (size_t)b * HID + (size_t)h * DH;
    const int wrow = wid * 16;

    // ---- stage Q + K/V tile 0 ----
#pragma unroll
    for (int i = 0; i < 4; i++) {
        int f = tid + i * 256;
        int row = f >> 3;
        int dc = (f & 7) * 8;
        cp16(smem_u32(&QS[row * AKS + dc]),
             qh + (size_t)(q0 + row) * ROWSTR + hoff + dc);
    }
#pragma unroll
    for (int i = 0; i < 2; i++) {
        int f = tid + i * 256;
        int row = f >> 3;
        int dc = (f & 7) * 8;
        cp16(smem_u32(&KB[row * AKS + dc]), kh + (size_t)row * ROWSTR + hoff + dc);
        cp16(smem_u32(&VB[row * AKS + dc]), vh + (size_t)row * ROWSTR + hoff + dc);
    }
    cp_commit();

    // V padding cols: col 64 = 1.0 bf16, 65..71 = 0, both buffers
    for (int i = tid; i < 2 * 64 * 8; i += 256) {
        int bufrow = i >> 3;
        int c = i & 7;
        VB[bufrow * AKS + 64 + c] = (c == 0) ? (uint16_t)0x3F80 : (uint16_t)0;
    }

    // hoisted per-lane ldmatrix bases
    const uint32_t kbase =
        smem_u32(KB) + (((lane & 7) + (lane >> 4) * 8) * AKS + ((lane >> 3) & 1) * 8) * 2;
    const uint32_t vbase =
        smem_u32(VB) + (((lane & 7) + ((lane >> 3) & 1) * 8) * AKS + (lane >> 4) * 8) * 2;
    const uint32_t vobase =
        smem_u32(VB) + (((lane & 7) + ((lane >> 3) & 1) * 8) * AKS + 64) * 2;

    cp_wait<0>();
    __syncthreads();

    // ---- persistent Q fragments ----
    uint32_t qa[4][4];
#pragma unroll
    for (int kt = 0; kt < 4; kt++)
        ldsm_x4(qa[kt][0], qa[kt][1], qa[kt][2], qa[kt][3],
                smem_u32(&QS[(wrow + (lane & 15)) * AKS + kt * 16 + (lane >> 4) * 8]));

    float O[8][4], Oex[4];
#pragma unroll
    for (int nt = 0; nt < 8; nt++)
#pragma unroll
        for (int j = 0; j < 4; j++) O[nt][j] = 0.f;
#pragma unroll
    for (int j = 0; j < 4; j++) Oex[j] = 0.f;
    float m0r = -1e30f, m1r = -1e30f;

    for (int it = 0; it < TSEQ / 64; it++) {
        const uint32_t bo = (uint32_t)(it & 1) * KVBYTES;

        if (it > 0) {
            cp_wait<0>();
            __syncthreads();
        }
        if (it < TSEQ / 64 - 1) {
            int s0n = (it + 1) * 64;
            uint16_t* Kn = KB + ((it + 1) & 1) * 64 * AKS;
            uint16_t* Vn = VB + ((it + 1) & 1) * 64 * AKS;
#pragma unroll
            for (int i = 0; i < 2; i++) {
                int f = tid + i * 256;
                int row = f >> 3;
                int dc = (f & 7) * 8;
                cp16(smem_u32(&Kn[row * AKS + dc]),
                     kh + (size_t)(s0n + row) * ROWSTR + hoff + dc);
                cp16(smem_u32(&Vn[row * AKS + dc]),
                     vh + (size_t)(s0n + row) * ROWSTR + hoff + dc);
            }
            cp_commit();
        }

        // ---- S = Q K^T (log2-domain scores) ----
        float sacc[8][4];
#pragma unroll
        for (int nt = 0; nt < 8; nt++)
#pragma unroll
            for (int j = 0; j < 4; j++) sacc[nt][j] = 0.f;
        const uint32_t kb = kbase + bo;
#pragma unroll
        for (int ntp = 0; ntp < 4; ntp++) {
#pragma unroll
            for (int kt = 0; kt < 4; kt++) {
                uint32_t r0, r1, r2, r3;
                ldsm_x4(r0, r1, r2, r3, kb + (ntp * 16 * AKS + kt * 16) * 2);
                uint32_t blo[2] = {r0, r1}, bhi[2] = {r2, r3};
                mma_bf16(sacc[2 * ntp], qa[kt], blo);
                mma_bf16(sacc[2 * ntp + 1], qa[kt], bhi);
            }
        }

        // ---- online softmax: max, vote-rescale, bf16x2 ex2 ----
        float mx0 = -1e30f, mx1 = -1e30f;
#pragma unroll
        for (int nt = 0; nt < 8; nt++) {
            mx0 = fmaxf(mx0, fmaxf(sacc[nt][0], sacc[nt][1]));
            mx1 = fmaxf(mx1, fmaxf(sacc[nt][2], sacc[nt][3]));
        }
        mx0 = fmaxf(mx0, __shfl_xor_sync(0xffffffff, mx0, 1));
        mx0 = fmaxf(mx0, __shfl_xor_sync(0xffffffff, mx0, 2));
        mx1 = fmaxf(mx1, __shfl_xor_sync(0xffffffff, mx1, 1));
        mx1 = fmaxf(mx1, __shfl_xor_sync(0xffffffff, mx1, 2));

        const float mn0 = fmaxf(m0r, mx0), mn1 = fmaxf(m1r, mx1);
        bool upd = (mn0 > m0r) || (mn1 > m1r);
        if (__any_sync(0xffffffffu, upd)) {
            float f0 = ex2(m0r - mn0), f1 = ex2(m1r - mn1);
            m0r = mn0; m1r = mn1;
#pragma unroll
            for (int nt = 0; nt < 8; nt++) {
                O[nt][0] *= f0; O[nt][1] *= f0;
                O[nt][2] *= f1; O[nt][3] *= f1;
            }
            Oex[0] *= f0; Oex[1] *= f0; Oex[2] *= f1; Oex[3] *= f1;
        }

        uint32_t pa[4][4];
#pragma unroll
        for (int nt = 0; nt < 8; nt++) {
            uint32_t dlo = pack_bf16(sacc[nt][0] - mn0, sacc[nt][1] - mn0);
            uint32_t dhi = pack_bf16(sacc[nt][2] - mn1, sacc[nt][3] - mn1);
            uint32_t p01 = ex2b2(dlo);
            uint32_t p23 = ex2b2(dhi);
            int kt = nt >> 1;
            if ((nt & 1) == 0) { pa[kt][0] = p01; pa[kt][1] = p23; }
            else               { pa[kt][2] = p01; pa[kt][3] = p23; }
        }

        // ---- O += P V  (+ ones-column row sums) ----
        const uint32_t vb = vbase + bo;
        const uint32_t vo = vobase + bo;
#pragma unroll
        for (int ntp = 0; ntp < 4; ntp++) {
#pragma unroll
            for (int kt = 0; kt < 4; kt++) {
                uint32_t r0, r1, r2, r3;
                ldsm_x4t(r0, r1, r2, r3, vb + (kt * 16 * AKS + ntp * 16) * 2);
                uint32_t blo[2] = {r0, r1}, bhi[2] = {r2, r3};
                mma_bf16(O[2 * ntp], pa[kt], blo);
                mma_bf16(O[2 * ntp + 1], pa[kt], bhi);
            }
        }
#pragma unroll
        for (int kt = 0; kt < 4; kt++) {
            uint32_t r0, r1;
            ldsm_x2t(r0, r1, vo + (kt * 16 * AKS) * 2);
            uint32_t bx[2] = {r0, r1};
            mma_bf16(Oex, pa[kt], bx);
        }
    }

    // ---- epilogue: row sums from quad leader, normalize, store ----
    const int qlead = lane & ~3;
    float l0 = __shfl_sync(0xffffffff, Oex[0], qlead);
    float l1 = __shfl_sync(0xffffffff, Oex[2], qlead);
    float il0 = 1.f / l0, il1 = 1.f / l1;
    const int gr0 = q0 + wrow + g, gr1 = gr0 + 8;
#pragma unroll
    for (int nt = 0; nt < 8; nt++) {
        int col = nt * 8 + 2 * t;
        float2 o0 = {O[nt][0] * il0, O[nt][1] * il0};
        float2 o1 = {O[nt][2] * il1, O[nt][3] * il1};
        *reinterpret_cast<float2*>(out + (size_t)gr0 * ROWSTR + hoff + col) = o0;
        *reinterpret_cast<float2*>(out + (size_t)gr1 * ROWSTR + hoff + col) = o1;
    }
}

// =================================================================
extern "C" void kernel_launch(void* const* d_in, const int* in_sizes, int n_in,
                              void* d_out, int out_size)
{
    const float* q  = (const float*)d_in[0];
    const float* k  = (const float*)d_in[1];
    const float* v  = (const float*)d_in[2];
    const float* Wq = (const float*)d_in[3];
    const float* bq = (const float*)d_in[4];
    const float* Wk = (const float*)d_in[5];
    const float* bk = (const float*)d_in[6];
    const float* Wv = (const float*)d_in[7];
    const float* bv = (const float*)d_in[8];
    float* out = (float*)d_out;

    __nv_bfloat16 *qh, *kh, *vh, *xq, *xk, *xv, *wq, *wk, *wv;
    cudaGetSymbolAddress((void**)&qh, g_qh);
    cudaGetSymbolAddress((void**)&kh, g_kh);
    cudaGetSymbolAddress((void**)&vh, g_vh);
    cudaGetSymbolAddress((void**)&xq, g_xq);
    cudaGetSymbolAddress((void**)&xk, g_xk);
    cudaGetSymbolAddress((void**)&xv, g_xv);
    cudaGetSymbolAddress((void**)&wq, g_wq);
    cudaGetSymbolAddress((void**)&wk, g_wk);
    cudaGetSymbolAddress((void**)&wv, g_wv);

    const int n4i = MR * HID / 4;
    const int n4w = HID * HID / 4;
    cvt3_kernel<<<dim3(n4i / 256, 3), 256>>>(q, k, v, xq, xk, xv, n4i);
    cvt3_kernel<<<dim3(n4w / 256, 3), 256>>>(Wq, Wk, Wv, wq, wk, wv, n4w);

    cudaFuncSetAttribute(proj_kernel,
                         cudaFuncAttributeMaxDynamicSharedMemorySize, PJ_SMEM);
    dim3 pg(HID / 128, MR / 128, 3);
    proj_kernel<<<pg, 256, PJ_SMEM>>>(
        xq, wq, bq, qh,
        xk, wk, bk, kh,
        xv, wv, bv, vh,
        0.125f * LOG2E);

    cudaFuncSetAttribute(attn_kernel,
                         cudaFuncAttributeMaxDynamicSharedMemorySize, ATT_SMEM);
    dim3 ag(TT / 128, NH, BB);
    attn_kernel<<<ag, 256, ATT_SMEM>>>(qh, kh, vh, out);
}

// round 8
// speedup vs baseline: 7.9944x; 1.0267x over previous
#include <cuda_runtime.h>
#include <cuda_bf16.h>
#include <cstdint>

#define HID 1024
#define NH 16
#define DH 64
#define TT 2048
#define TSEQ 2048
#define BB 4
#define MR (TT*BB)          // 8192 rows for projections
#define ROWSTR (BB*HID)     // 4096 elements per t-step
#define LOG2E 1.4426950408889634f

// ---------------- scratch ----------------
__device__ __nv_bfloat16 g_qh[(size_t)MR * HID];
__device__ __nv_bfloat16 g_kh[(size_t)MR * HID];
__device__ __nv_bfloat16 g_vh[(size_t)MR * HID];
__device__ __nv_bfloat16 g_xq[(size_t)MR * HID];
__device__ __nv_bfloat16 g_xk[(size_t)MR * HID];
__device__ __nv_bfloat16 g_xv[(size_t)MR * HID];
__device__ __nv_bfloat16 g_wq[(size_t)HID * HID];
__device__ __nv_bfloat16 g_wk[(size_t)HID * HID];
__device__ __nv_bfloat16 g_wv[(size_t)HID * HID];

// ---------------- helpers ----------------
__device__ __forceinline__ uint32_t pack_bf16(float lo, float hi) {
    uint32_t d;
    asm("cvt.rn.bf16x2.f32 %0, %1, %2;" : "=r"(d) : "f"(hi), "f"(lo));
    return d;
}
__device__ __forceinline__ float ex2(float x) {
    float r; asm("ex2.approx.f32 %0, %1;" : "=f"(r) : "f"(x)); return r;
}
__device__ __forceinline__ uint32_t ex2b2(uint32_t x) {
    uint32_t r; asm("ex2.approx.ftz.bf16x2 %0, %1;" : "=r"(r) : "r"(x)); return r;
}
__device__ __forceinline__ uint32_t smem_u32(const void* p) {
    return (uint32_t)__cvta_generic_to_shared(p);
}
__device__ __forceinline__ void ldsm_x4(uint32_t& r0, uint32_t& r1,
                                        uint32_t& r2, uint32_t& r3, uint32_t a) {
    asm volatile("ldmatrix.sync.aligned.m8n8.x4.shared.b16 {%0,%1,%2,%3}, [%4];"
                 : "=r"(r0), "=r"(r1), "=r"(r2), "=r"(r3) : "r"(a));
}
__device__ __forceinline__ void ldsm_x4t(uint32_t& r0, uint32_t& r1,
                                         uint32_t& r2, uint32_t& r3, uint32_t a) {
    asm volatile("ldmatrix.sync.aligned.m8n8.x4.trans.shared.b16 {%0,%1,%2,%3}, [%4];"
                 : "=r"(r0), "=r"(r1), "=r"(r2), "=r"(r3) : "r"(a));
}
__device__ __forceinline__ void ldsm_x2t(uint32_t& r0, uint32_t& r1, uint32_t a) {
    asm volatile("ldmatrix.sync.aligned.m8n8.x2.trans.shared.b16 {%0,%1}, [%2];"
                 : "=r"(r0), "=r"(r1) : "r"(a));
}
__device__ __forceinline__ void mma_bf16(float* c, const uint32_t* a, const uint32_t* b) {
    asm volatile(
        "mma.sync.aligned.m16n8k16.row.col.f32.bf16.bf16.f32 "
        "{%0,%1,%2,%3}, {%4,%5,%6,%7}, {%8,%9}, {%0,%1,%2,%3};"
        : "+f"(c[0]), "+f"(c[1]), "+f"(c[2]), "+f"(c[3])
        : "r"(a[0]), "r"(a[1]), "r"(a[2]), "r"(a[3]), "r"(b[0]), "r"(b[1]));
}
__device__ __forceinline__ void cp16(uint32_t dst, const void* src) {
    asm volatile("cp.async.cg.shared.global [%0], [%1], 16;" :: "r"(dst), "l"(src) : "memory");
}
__device__ __forceinline__ void cp_commit() {
    asm volatile("cp.async.commit_group;" ::: "memory");
}
template <int N> __device__ __forceinline__ void cp_wait() {
    asm volatile("cp.async.wait_group %0;" :: "n"(N) : "memory");
}

// =================================================================
// fp32 -> bf16 convert, 3 arrays per launch (y-indexed)
// =================================================================
__global__ __launch_bounds__(256) void cvt3_kernel(
    const float* __restrict__ s0, const float* __restrict__ s1,
    const float* __restrict__ s2, __nv_bfloat16* __restrict__ d0,
    __nv_bfloat16* __restrict__ d1, __nv_bfloat16* __restrict__ d2, int n4)
{
    const float* src = (blockIdx.y == 0) ? s0 : (blockIdx.y == 1) ? s1 : s2;
    __nv_bfloat16* dst = (blockIdx.y == 0) ? d0 : (blockIdx.y == 1) ? d1 : d2;
    int i = blockIdx.x * blockDim.x + threadIdx.x;
    if (i < n4) {
        float4 v = reinterpret_cast<const float4*>(src)[i];
        reinterpret_cast<uint2*>(dst)[i] =
            make_uint2(pack_bf16(v.x, v.y), pack_bf16(v.z, v.w));
    }
}

// =================================================================
// Projection: Y = ReLU6(X @ W^T + bias) * scale, all-bf16 mma.sync
// 128x128 tile, BK=64, 256 threads, cp.async double buffered.
// =================================================================
#define PJS 72
#define PJ_TILE (128 * PJS)
#define PJ_STAGE (2 * PJ_TILE)
#define PJ_STAGE_BYTES (PJ_STAGE * 2)
#define PJ_SMEM (2 * PJ_STAGE * 2)

__global__ __launch_bounds__(256, 2) void proj_kernel(
    const __nv_bfloat16* __restrict__ Xq, const __nv_bfloat16* __restrict__ Wq,
    const float* __restrict__ bq, __nv_bfloat16* __restrict__ Yq,
    const __nv_bfloat16* __restrict__ Xk, const __nv_bfloat16* __restrict__ Wk,
    const float* __restrict__ bk, __nv_bfloat16* __restrict__ Yk,
    const __nv_bfloat16* __restrict__ Xv, const __nv_bfloat16* __restrict__ Wv,
    const float* __restrict__ bv, __nv_bfloat16* __restrict__ Yv,
    float sq)
{
    extern __shared__ __align__(16) uint16_t psm[];

    const int tid = threadIdx.x;
    const int lane = tid & 31;
    const int wid = tid >> 5;
    const int g = lane >> 2;
    const int t = lane & 3;
    const int wm = (wid >> 2) * 64;
    const int wn = (wid & 3) * 32;
    const int z = blockIdx.z;
    const int m0 = blockIdx.y * 128;
    const int n0 = blockIdx.x * 128;

    const __nv_bfloat16* X = (z == 0) ? Xq : (z == 1) ? Xk : Xv;
    const __nv_bfloat16* W = (z == 0) ? Wq : (z == 1) ? Wk : Wv;
    const float*      bias = (z == 0) ? bq : (z == 1) ? bk : bv;
    __nv_bfloat16*       Y = (z == 0) ? Yq : (z == 1) ? Yk : Yv;
    const float      scale = (z == 0) ? sq : 1.0f;

    float acc[4][4][4];
#pragma unroll
    for (int mt = 0; mt < 4; mt++)
#pragma unroll
        for (int nt = 0; nt < 4; nt++)
#pragma unroll
            for (int j = 0; j < 4; j++) acc[mt][nt][j] = 0.f;

    const uint32_t smbase = smem_u32(psm);
    const uint32_t abase =
        smbase + ((wm + (lane & 15)) * PJS + (lane >> 4) * 8) * 2;
    const uint32_t bbase =
        smbase + PJ_TILE * 2 +
        ((wn + (lane & 7) + (lane >> 4) * 8) * PJS + ((lane >> 3) & 1) * 8) * 2;

    auto fill = [&](int s, int k0) {
        uint16_t* As = psm + s * PJ_STAGE;
        uint16_t* Bs = As + PJ_TILE;
#pragma unroll
        for (int i = 0; i < 4; i++) {
            int f = tid + i * 256;
            int row = f >> 3;
            int dc = (f & 7) * 8;
            cp16(smem_u32(&As[row * PJS + dc]),
                 X + (size_t)(m0 + row) * HID + k0 + dc);
            cp16(smem_u32(&Bs[row * PJS + dc]),
                 W + (size_t)(n0 + row) * HID + k0 + dc);
        }
        cp_commit();
    };

    fill(0, 0);

    for (int it = 0; it < 16; it++) {
        cp_wait<0>();
        __syncthreads();
        if (it < 15) fill((it + 1) & 1, (it + 1) * 64);

        const uint32_t so = (uint32_t)(it & 1) * PJ_STAGE_BYTES;
        const uint32_t ab = abase + so;
        const uint32_t bb = bbase + so;
#pragma unroll
        for (int kt = 0; kt < 4; kt++) {
            uint32_t af[4][4], bf[4][2];
#pragma unroll
            for (int mt = 0; mt < 4; mt++)
                ldsm_x4(af[mt][0], af[mt][1], af[mt][2], af[mt][3],
                        ab + (mt * 16 * PJS + kt * 16) * 2);
#pragma unroll
            for (int ntp = 0; ntp < 2; ntp++) {
                uint32_t r0, r1, r2, r3;
                ldsm_x4(r0, r1, r2, r3,
                        bb + (ntp * 16 * PJS + kt * 16) * 2);
                bf[2 * ntp][0] = r0; bf[2 * ntp][1] = r1;
                bf[2 * ntp + 1][0] = r2; bf[2 * ntp + 1][1] = r3;
            }
#pragma unroll
            for (int mt = 0; mt < 4; mt++)
#pragma unroll
                for (int nt = 0; nt < 4; nt++)
                    mma_bf16(acc[mt][nt], af[mt], bf[nt]);
        }
    }

#pragma unroll
    for (int nt = 0; nt < 4; nt++) {
        int col = n0 + wn + nt * 8 + 2 * t;
        float b0 = bias[col], b1 = bias[col + 1];
#pragma unroll
        for (int mt = 0; mt < 4; mt++) {
            int r0 = m0 + wm + mt * 16 + g;
            float o0 = fminf(fmaxf(acc[mt][nt][0] + b0, 0.f), 6.f) * scale;
            float o1 = fminf(fmaxf(acc[mt][nt][1] + b1, 0.f), 6.f) * scale;
            float o2 = fminf(fmaxf(acc[mt][nt][2] + b0, 0.f), 6.f) * scale;
            float o3 = fminf(fmaxf(acc[mt][nt][3] + b1, 0.f), 6.f) * scale;
            *reinterpret_cast<uint32_t*>(Y + (size_t)r0 * HID + col) = pack_bf16(o0, o1);
            *reinterpret_cast<uint32_t*>(Y + (size_t)(r0 + 8) * HID + col) = pack_bf16(o2, o3);
        }
    }
}

// =================================================================
// Flash attention, bf16 MMA, 4 warps x 32 Q rows: each K/V ldmatrix
// feeds TWO m16 MMAs (halves smem crossbar traffic per MMA).
// bf16x2 ex2 softmax, ones-column row sums, vote-skip rescale.
// =================================================================
#define AKS 72
#define QS_OFF 0
#define KB_OFF (128 * AKS * 2)
#define VB_OFF (KB_OFF + 2 * 64 * AKS * 2)
#define KVBYTES (64 * AKS * 2)
#define ATT_SMEM (VB_OFF + 2 * 64 * AKS * 2)   // 55296
#define ATH 128

__global__ __launch_bounds__(ATH, 2) void attn_kernel(
    const __nv_bfloat16* __restrict__ qh, const __nv_bfloat16* __restrict__ kh,
    const __nv_bfloat16* __restrict__ vh, float* __restrict__ out)
{
    extern __shared__ __align__(16) char sm[];
    uint16_t* QS = reinterpret_cast<uint16_t*>(sm + QS_OFF);
    uint16_t* KB = reinterpret_cast<uint16_t*>(sm + KB_OFF);
    uint16_t* VB = reinterpret_cast<uint16_t*>(sm + VB_OFF);

    const int tid = threadIdx.x;
    const int lane = tid & 31;
    const int wid = tid >> 5;          // 0..3
    const int g = lane >> 2;
    const int t = lane & 3;
    const int b = blockIdx.z, h = blockIdx.y;
    const int q0 = blockIdx.x * 128;
    const size_t hoff = (size_t)b * HID + (size_t)h * DH;
    const int wrow = wid * 32;         // 32 Q rows per warp

    // ---- stage Q + K/V tile 0 ----
#pragma unroll
    for (int i = 0; i < 8; i++) {
        int f = tid + i * ATH;
        int row = f >> 3;
        int dc = (f & 7) * 8;
        cp16(smem_u32(&QS[row * AKS + dc]),
             qh + (size_t)(q0 + row) * ROWSTR + hoff + dc);
    }
#pragma unroll
    for (int i = 0; i < 4; i++) {
        int f = tid + i * ATH;
        int row = f >> 3;
        int dc = (f & 7) * 8;
        cp16(smem_u32(&KB[row * AKS + dc]), kh + (size_t)row * ROWSTR + hoff + dc);
        cp16(smem_u32(&VB[row * AKS + dc]), vh + (size_t)row * ROWSTR + hoff + dc);
    }
    cp_commit();

    // V padding cols: col 64 = 1.0 bf16, 65..71 = 0, both buffers
    for (int i = tid; i < 2 * 64 * 8; i += ATH) {
        int bufrow = i >> 3;
        int c = i & 7;
        VB[bufrow * AKS + 64 + c] = (c == 0) ? (uint16_t)0x3F80 : (uint16_t)0;
    }

    // hoisted per-lane ldmatrix bases
    const uint32_t kbase =
        smem_u32(KB) + (((lane & 7) + (lane >> 4) * 8) * AKS + ((lane >> 3) & 1) * 8) * 2;
    const uint32_t vbase =
        smem_u32(VB) + (((lane & 7) + ((lane >> 3) & 1) * 8) * AKS + (lane >> 4) * 8) * 2;
    const uint32_t vobase =
        smem_u32(VB) + (((lane & 7) + ((lane >> 3) & 1) * 8) * AKS + 64) * 2;

    cp_wait<0>();
    __syncthreads();

    // ---- persistent Q fragments: 2 m-halves x 4 k-steps ----
    uint32_t qa[2][4][4];
#pragma unroll
    for (int mh = 0; mh < 2; mh++)
#pragma unroll
        for (int kt = 0; kt < 4; kt++)
            ldsm_x4(qa[mh][kt][0], qa[mh][kt][1], qa[mh][kt][2], qa[mh][kt][3],
                    smem_u32(&QS[(wrow + mh * 16 + (lane & 15)) * AKS +
                                 kt * 16 + (lane >> 4) * 8]));

    float O[2][8][4], Oex[2][4];
#pragma unroll
    for (int mh = 0; mh < 2; mh++) {
#pragma unroll
        for (int nt = 0; nt < 8; nt++)
#pragma unroll
            for (int j = 0; j < 4; j++) O[mh][nt][j] = 0.f;
#pragma unroll
        for (int j = 0; j < 4; j++) Oex[mh][j] = 0.f;
    }
    float mrun[2][2];
    mrun[0][0] = mrun[0][1] = mrun[1][0] = mrun[1][1] = -1e30f;

    for (int it = 0; it < TSEQ / 64; it++) {
        const uint32_t bo = (uint32_t)(it & 1) * KVBYTES;

        if (it > 0) {
            cp_wait<0>();
            __syncthreads();
        }
        if (it < TSEQ / 64 - 1) {
            int s0n = (it + 1) * 64;
            uint16_t* Kn = KB + ((it + 1) & 1) * 64 * AKS;
            uint16_t* Vn = VB + ((it + 1) & 1) * 64 * AKS;
#pragma unroll
            for (int i = 0; i < 4; i++) {
                int f = tid + i * ATH;
                int row = f >> 3;
                int dc = (f & 7) * 8;
                cp16(smem_u32(&Kn[row * AKS + dc]),
                     kh + (size_t)(s0n + row) * ROWSTR + hoff + dc);
                cp16(smem_u32(&Vn[row * AKS + dc]),
                     vh + (size_t)(s0n + row) * ROWSTR + hoff + dc);
            }
            cp_commit();
        }

        // ---- S = Q K^T, both m-halves share each K fragment ----
        float sacc[2][8][4];
#pragma unroll
        for (int mh = 0; mh < 2; mh++)
#pragma unroll
            for (int nt = 0; nt < 8; nt++)
#pragma unroll
                for (int j = 0; j < 4; j++) sacc[mh][nt][j] = 0.f;
        const uint32_t kb = kbase + bo;
#pragma unroll
        for (int ntp = 0; ntp < 4; ntp++) {
#pragma unroll
            for (int kt = 0; kt < 4; kt++) {
                uint32_t r0, r1, r2, r3;
                ldsm_x4(r0, r1, r2, r3, kb + (ntp * 16 * AKS + kt * 16) * 2);
                uint32_t blo[2] = {r0, r1}, bhi[2] = {r2, r3};
#pragma unroll
                for (int mh = 0; mh < 2; mh++) {
                    mma_bf16(sacc[mh][2 * ntp], qa[mh][kt], blo);
                    mma_bf16(sacc[mh][2 * ntp + 1], qa[mh][kt], bhi);
                }
            }
        }

        // ---- online softmax per m-half ----
        float mn[2][2], fs[2][2];
        bool upd = false;
#pragma unroll
        for (int mh = 0; mh < 2; mh++) {
            float mx0 = -1e30f, mx1 = -1e30f;
#pragma unroll
            for (int nt = 0; nt < 8; nt++) {
                mx0 = fmaxf(mx0, fmaxf(sacc[mh][nt][0], sacc[mh][nt][1]));
                mx1 = fmaxf(mx1, fmaxf(sacc[mh][nt][2], sacc[mh][nt][3]));
            }
            mx0 = fmaxf(mx0, __shfl_xor_sync(0xffffffff, mx0, 1));
            mx0 = fmaxf(mx0, __shfl_xor_sync(0xffffffff, mx0, 2));
            mx1 = fmaxf(mx1, __shfl_xor_sync(0xffffffff, mx1, 1));
            mx1 = fmaxf(mx1, __shfl_xor_sync(0xffffffff, mx1, 2));
            mn[mh][0] = fmaxf(mrun[mh][0], mx0);
            mn[mh][1] = fmaxf(mrun[mh][1], mx1);
            upd |= (mn[mh][0] > mrun[mh][0]) || (mn[mh][1] > mrun[mh][1]);
        }
        if (__any_sync(0xffffffffu, upd)) {
#pragma unroll
            for (int mh = 0; mh < 2; mh++) {
                fs[mh][0] = ex2(mrun[mh][0] - mn[mh][0]);
                fs[mh][1] = ex2(mrun[mh][1] - mn[mh][1]);
                mrun[mh][0] = mn[mh][0]; mrun[mh][1] = mn[mh][1];
#pragma unroll
                for (int nt = 0; nt < 8; nt++) {
                    O[mh][nt][0] *= fs[mh][0]; O[mh][nt][1] *= fs[mh][0];
                    O[mh][nt][2] *= fs[mh][1]; O[mh][nt][3] *= fs[mh][1];
                }
                Oex[mh][0] *= fs[mh][0]; Oex[mh][1] *= fs[mh][0];
                Oex[mh][2] *= fs[mh][1]; Oex[mh][3] *= fs[mh][1];
            }
        }

        uint32_t pa[2][4][4];
#pragma unroll
        for (int mh = 0; mh < 2; mh++)
#pragma unroll
            for (int nt = 0; nt < 8; nt++) {
                uint32_t dlo = pack_bf16(sacc[mh][nt][0] - mn[mh][0],
                                         sacc[mh][nt][1] - mn[mh][0]);
                uint32_t dhi = pack_bf16(sacc[mh][nt][2] - mn[mh][1],
                                         sacc[mh][nt][3] - mn[mh][1]);
                uint32_t p01 = ex2b2(dlo);
                uint32_t p23 = ex2b2(dhi);
                int kt = nt >> 1;
                if ((nt & 1) == 0) { pa[mh][kt][0] = p01; pa[mh][kt][1] = p23; }
                else               { pa[mh][kt][2] = p01; pa[mh][kt][3] = p23; }
            }

        // ---- O += P V, both m-halves share each V fragment ----
        const uint32_t vb = vbase + bo;
        const uint32_t vo = vobase + bo;
#pragma unroll
        for (int ntp = 0; ntp < 4; ntp++) {
#pragma unroll
            for (int kt = 0; kt < 4; kt++) {
                uint32_t r0, r1, r2, r3;
                ldsm_x4t(r0, r1, r2, r3, vb + (kt * 16 * AKS + ntp * 16) * 2);
                uint32_t blo[2] = {r0, r1}, bhi[2] = {r2, r3};
#pragma unroll
                for (int mh = 0; mh < 2; mh++) {
                    mma_bf16(O[mh][2 * ntp], pa[mh][kt], blo);
                    mma_bf16(O[mh][2 * ntp + 1], pa[mh][kt], bhi);
                }
            }
        }
#pragma unroll
        for (int kt = 0; kt < 4; kt++) {
            uint32_t r0, r1;
            ldsm_x2t(r0, r1, vo + (kt * 16 * AKS) * 2);
            uint32_t bx[2] = {r0, r1};
#pragma unroll
            for (int mh = 0; mh < 2; mh++)
                mma_bf16(Oex[mh], pa[mh][kt], bx);
        }
    }

    // ---- epilogue: row sums from quad leader, normalize, store ----
    const int qlead = lane & ~3;
#pragma unroll
    for (int mh = 0; mh < 2; mh++) {
        float l0 = __shfl_sync(0xffffffff, Oex[mh][0], qlead);
        float l1 = __shfl_sync(0xffffffff, Oex[mh][2], qlead);
        float il0 = 1.f / l0, il1 = 1.f / l1;
        const int gr0 = q0 + wrow + mh * 16 + g, gr1 = gr0 + 8;
#pragma unroll
        for (int nt = 0; nt < 8; nt++) {
            int col = nt * 8 + 2 * t;
            float2 o0 = {O[mh][nt][0] * il0, O[mh][nt][1] * il0};
            float2 o1 = {O[mh][nt][2] * il1, O[mh][nt][3] * il1};
            *reinterpret_cast<float2*>(out + (size_t)gr0 * ROWSTR + hoff + col) = o0;
            *reinterpret_cast<float2*>(out + (size_t)gr1 * ROWSTR + hoff + col) = o1;
        }
    }
}

// =================================================================
extern "C" void kernel_launch(void* const* d_in, const int* in_sizes, int n_in,
                              void* d_out, int out_size)
{
    const float* q  = (const float*)d_in[0];
    const float* k  = (const float*)d_in[1];
    const float* v  = (const float*)d_in[2];
    const float* Wq = (const float*)d_in[3];
    const float* bq = (const float*)d_in[4];
    const float* Wk = (const float*)d_in[5];
    const float* bk = (const float*)d_in[6];
    const float* Wv = (const float*)d_in[7];
    const float* bv = (const float*)d_in[8];
    float* out = (float*)d_out;

    __nv_bfloat16 *qh, *kh, *vh, *xq, *xk, *xv, *wq, *wk, *wv;
    cudaGetSymbolAddress((void**)&qh, g_qh);
    cudaGetSymbolAddress((void**)&kh, g_kh);
    cudaGetSymbolAddress((void**)&vh, g_vh);
    cudaGetSymbolAddress((void**)&xq, g_xq);
    cudaGetSymbolAddress((void**)&xk, g_xk);
    cudaGetSymbolAddress((void**)&xv, g_xv);
    cudaGetSymbolAddress((void**)&wq, g_wq);
    cudaGetSymbolAddress((void**)&wk, g_wk);
    cudaGetSymbolAddress((void**)&wv, g_wv);

    const int n4i = MR * HID / 4;
    const int n4w = HID * HID / 4;
    cvt3_kernel<<<dim3(n4i / 256, 3), 256>>>(q, k, v, xq, xk, xv, n4i);
    cvt3_kernel<<<dim3(n4w / 256, 3), 256>>>(Wq, Wk, Wv, wq, wk, wv, n4w);

    cudaFuncSetAttribute(proj_kernel,
                         cudaFuncAttributeMaxDynamicSharedMemorySize, PJ_SMEM);
    dim3 pg(HID / 128, MR / 128, 3);
    proj_kernel<<<pg, 256, PJ_SMEM>>>(
        xq, wq, bq, qh,
        xk, wk, bk, kh,
        xv, wv, bv, vh,
        0.125f * LOG2E);

    cudaFuncSetAttribute(attn_kernel,
                         cudaFuncAttributeMaxDynamicSharedMemorySize, ATT_SMEM);
    dim3 ag(TT / 128, NH, BB);
    attn_kernel<<<ag, ATH, ATT_SMEM>>>(qh, kh, vh, out);
}